// round 1
// baseline (speedup 1.0000x reference)
#include <cuda_runtime.h>
#include <math.h>

#define DIM    768
#define DSTATE 16
#define DCONV  4
#define EE     1536          // expand dim
#define BB     2
#define LL     2048
#define BL     (BB*LL)       // 4096
#define EPS    1e-6f

// ---------------- scratch (static device arrays; no allocations) -------------
__device__ float g_xn[BL * DIM];   // rmsnorm output
__device__ float g_xp[BL * EE];    // after in-proj
__device__ float g_xc[BL * EE];    // after depthwise conv
__device__ float g_y [BL * EE];    // after SSM scan

// ---------------- rmsnorm ----------------------------------------------------
__global__ void rmsnorm_kernel(const float* __restrict__ x,
                               const float* __restrict__ gamma,
                               float* __restrict__ xn)
{
    const int row = blockIdx.x;              // 0..BL-1
    const float* xr = x + (size_t)row * DIM;
    float* or_ = xn + (size_t)row * DIM;

    // 768 elems, 256 threads -> 3 each
    float v0 = xr[threadIdx.x];
    float v1 = xr[threadIdx.x + 256];
    float v2 = xr[threadIdx.x + 512];
    float ss = v0 * v0 + v1 * v1 + v2 * v2;

    // warp reduce
    #pragma unroll
    for (int o = 16; o > 0; o >>= 1)
        ss += __shfl_xor_sync(0xffffffffu, ss, o);

    __shared__ float warp_s[8];
    int wid = threadIdx.x >> 5, lane = threadIdx.x & 31;
    if (lane == 0) warp_s[wid] = ss;
    __syncthreads();
    if (wid == 0) {
        float t = (lane < 8) ? warp_s[lane] : 0.f;
        #pragma unroll
        for (int o = 4; o > 0; o >>= 1)
            t += __shfl_xor_sync(0xffffffffu, t, o);
        if (lane == 0) warp_s[0] = t;
    }
    __syncthreads();
    float sumsq = warp_s[0];
    float rms = sqrtf(sumsq * (1.0f / DIM));
    float inv = 1.0f / (rms + EPS);

    or_[threadIdx.x]       = gamma[threadIdx.x]       * v0 * inv;
    or_[threadIdx.x + 256] = gamma[threadIdx.x + 256] * v1 * inv;
    or_[threadIdx.x + 512] = gamma[threadIdx.x + 512] * v2 * inv;
}

// ---------------- GEMM: C[M,N] = A[M,K] * B[N,K]^T + bias (+resid) ----------
// BM=BN=128, BK=16, 256 threads, 8x8 microtile.
template<bool RESID>
__global__ __launch_bounds__(256)
void gemm_nt_kernel(const float* __restrict__ A,
                    const float* __restrict__ Bm,
                    const float* __restrict__ bias,
                    const float* __restrict__ resid,
                    float* __restrict__ Cout,
                    int M, int N, int K)
{
    __shared__ float As[16][128];
    __shared__ float Bs[16][128];

    const int tid = threadIdx.x;
    const int tx = tid & 15;        // 0..15 -> col group
    const int ty = tid >> 4;        // 0..15 -> row group
    const int brow = blockIdx.y * 128;
    const int bcol = blockIdx.x * 128;

    float acc[8][8];
    #pragma unroll
    for (int i = 0; i < 8; i++)
        #pragma unroll
        for (int j = 0; j < 8; j++) acc[i][j] = 0.f;

    for (int kt = 0; kt < K; kt += 16) {
        // load 128x16 tiles of A and B, transposed into shared
        #pragma unroll
        for (int i = 0; i < 2; i++) {
            int f  = tid + i * 256;          // float4 index, 0..511
            int r  = f >> 2;                 // tile row 0..127
            int c4 = (f & 3) * 4;            // k offset 0,4,8,12
            float4 va = *(const float4*)&A [(size_t)(brow + r) * K + kt + c4];
            As[c4 + 0][r] = va.x; As[c4 + 1][r] = va.y;
            As[c4 + 2][r] = va.z; As[c4 + 3][r] = va.w;
            float4 vb = *(const float4*)&Bm[(size_t)(bcol + r) * K + kt + c4];
            Bs[c4 + 0][r] = vb.x; Bs[c4 + 1][r] = vb.y;
            Bs[c4 + 2][r] = vb.z; Bs[c4 + 3][r] = vb.w;
        }
        __syncthreads();

        #pragma unroll
        for (int kk = 0; kk < 16; kk++) {
            float a[8], b[8];
            *(float4*)(a)     = *(const float4*)&As[kk][ty * 8];
            *(float4*)(a + 4) = *(const float4*)&As[kk][ty * 8 + 4];
            *(float4*)(b)     = *(const float4*)&Bs[kk][tx * 8];
            *(float4*)(b + 4) = *(const float4*)&Bs[kk][tx * 8 + 4];
            #pragma unroll
            for (int i = 0; i < 8; i++)
                #pragma unroll
                for (int j = 0; j < 8; j++)
                    acc[i][j] = fmaf(a[i], b[j], acc[i][j]);
        }
        __syncthreads();
    }

    // epilogue
    #pragma unroll
    for (int i = 0; i < 8; i++) {
        int r = brow + ty * 8 + i;
        #pragma unroll
        for (int j = 0; j < 8; j += 4) {
            int c = bcol + tx * 8 + j;
            float4 bv = *(const float4*)&bias[c];
            float4 o;
            o.x = acc[i][j + 0] + bv.x;
            o.y = acc[i][j + 1] + bv.y;
            o.z = acc[i][j + 2] + bv.z;
            o.w = acc[i][j + 3] + bv.w;
            if (RESID) {
                float4 rv = *(const float4*)&resid[(size_t)r * N + c];
                o.x += rv.x; o.y += rv.y; o.z += rv.z; o.w += rv.w;
            }
            *(float4*)&Cout[(size_t)r * N + c] = o;
        }
    }
}

// ---------------- depthwise causal conv (width 4) ----------------------------
__global__ void conv_kernel(const float* __restrict__ xp,
                            const float* __restrict__ convw,
                            float* __restrict__ xc)
{
    int idx = blockIdx.x * blockDim.x + threadIdx.x;   // over BL*EE
    if (idx >= BL * EE) return;
    int e = idx % EE;
    int bt = idx / EE;           // b*LL + t
    int t = bt % LL;

    float w0 = convw[e * 4 + 0];
    float w1 = convw[e * 4 + 1];
    float w2 = convw[e * 4 + 2];
    float w3 = convw[e * 4 + 3];

    float acc = xp[idx] * w3;                       // k=3 -> offset 0
    if (t >= 1) acc += xp[idx - EE]     * w2;
    if (t >= 2) acc += xp[idx - 2 * EE] * w1;
    if (t >= 3) acc += xp[idx - 3 * EE] * w0;
    xc[idx] = acc;
}

// ---------------- SSM scan ---------------------------------------------------
// 16 lanes per chain (one lane per state), 2 chains per warp.
__device__ __forceinline__ float sigmoidf_(float v) {
    return 1.0f / (1.0f + expf(-v));
}

__global__ void scan_kernel(const float* __restrict__ xc,
                            const float* __restrict__ A,
                            const float* __restrict__ Bp,
                            const float* __restrict__ C,
                            float* __restrict__ y)
{
    int gtid = blockIdx.x * blockDim.x + threadIdx.x;
    int warp = gtid >> 5;
    int lane = threadIdx.x & 31;
    int sub  = lane >> 4;           // 0 or 1: which chain in the pair
    int n    = lane & 15;           // state index

    int chain = warp * 2 + sub;     // 0..BB*EE-1
    int b = chain / EE;
    int e = chain % EE;

    float sA = sigmoidf_(A [e * DSTATE + n]);
    float sB = sigmoidf_(Bp[e * DSTATE + n]);
    float sC = sigmoidf_(C [e * DSTATE + n]);

    const float* xptr = xc + (size_t)b * LL * EE + e;
    float*       yptr = y  + (size_t)b * LL * EE + e;

    float h = 0.f;
    #pragma unroll 4
    for (int t = 0; t < LL; t++) {
        float xv = xptr[(size_t)t * EE];
        h = fmaf(sA, h, sB * xv);
        float p = h * sC;
        p += __shfl_xor_sync(0xffffffffu, p, 8, 16);
        p += __shfl_xor_sync(0xffffffffu, p, 4, 16);
        p += __shfl_xor_sync(0xffffffffu, p, 2, 16);
        p += __shfl_xor_sync(0xffffffffu, p, 1, 16);
        if (n == 0) yptr[(size_t)t * EE] = p;
    }
}

// ---------------- launch -----------------------------------------------------
extern "C" void kernel_launch(void* const* d_in, const int* in_sizes, int n_in,
                              void* d_out, int out_size)
{
    const float* x      = (const float*)d_in[0];
    const float* gamma  = (const float*)d_in[1];
    const float* W_in   = (const float*)d_in[2];
    const float* b_in   = (const float*)d_in[3];
    const float* conv_w = (const float*)d_in[4];
    const float* A      = (const float*)d_in[5];
    const float* Bp     = (const float*)d_in[6];
    const float* C      = (const float*)d_in[7];
    const float* W_out  = (const float*)d_in[8];
    const float* b_out  = (const float*)d_in[9];
    float* out = (float*)d_out;

    float *xn, *xp, *xc, *y;
    cudaGetSymbolAddress((void**)&xn, g_xn);
    cudaGetSymbolAddress((void**)&xp, g_xp);
    cudaGetSymbolAddress((void**)&xc, g_xc);
    cudaGetSymbolAddress((void**)&y,  g_y);

    // 1. rmsnorm
    rmsnorm_kernel<<<BL, 256>>>(x, gamma, xn);

    // 2. in-proj: xp[BL,EE] = xn[BL,DIM] @ W_in[EE,DIM]^T + b_in
    {
        dim3 grid(EE / 128, BL / 128);
        gemm_nt_kernel<false><<<grid, 256>>>(xn, W_in, b_in, nullptr, xp,
                                             BL, EE, DIM);
    }

    // 3. depthwise conv
    {
        int total = BL * EE;
        conv_kernel<<<(total + 255) / 256, 256>>>(xp, conv_w, xc);
    }

    // 4. SSM scan
    {
        // BB*EE chains, 16 lanes/chain, 2 chains/warp -> BB*EE/2 warps
        int warps = (BB * EE) / 2;           // 1536
        int threads_total = warps * 32;      // 49152
        scan_kernel<<<threads_total / 256, 256>>>(xc, A, Bp, C, y);
    }

    // 5. out-proj + residual: out = y @ W_out^T + b_out + x
    {
        dim3 grid(DIM / 128, BL / 128);
        gemm_nt_kernel<true><<<grid, 256>>>(y, W_out, b_out, x, out,
                                            BL, DIM, EE);
    }
}

// round 2
// speedup vs baseline: 1.2419x; 1.2419x over previous
#include <cuda_runtime.h>
#include <math.h>

#define DIM    768
#define DSTATE 16
#define DCONV  4
#define EE     1536          // expand dim
#define BB     2
#define LL     2048
#define BL     (BB*LL)       // 4096
#define EPS    1e-6f

#define CH     128           // chunk length
#define NCH    (LL/CH)       // 16 chunks

// ---------------- scratch (static device arrays; no allocations) -------------
__device__ float g_xn  [BL * DIM];             // rmsnorm output
__device__ float g_xp  [BL * EE];              // after in-proj
__device__ float g_y   [BL * EE];              // after SSM scan
__device__ float g_hloc[BB * NCH * DSTATE * EE];  // per-chunk local final states
__device__ float g_hin [BB * NCH * DSTATE * EE];  // per-chunk incoming states

__device__ __forceinline__ float sigmoidf_(float v) {
    return 1.0f / (1.0f + expf(-v));
}

// ---------------- rmsnorm ----------------------------------------------------
__global__ void rmsnorm_kernel(const float* __restrict__ x,
                               const float* __restrict__ gamma,
                               float* __restrict__ xn)
{
    const int row = blockIdx.x;              // 0..BL-1
    const float* xr = x + (size_t)row * DIM;
    float* or_ = xn + (size_t)row * DIM;

    float v0 = xr[threadIdx.x];
    float v1 = xr[threadIdx.x + 256];
    float v2 = xr[threadIdx.x + 512];
    float ss = v0 * v0 + v1 * v1 + v2 * v2;

    #pragma unroll
    for (int o = 16; o > 0; o >>= 1)
        ss += __shfl_xor_sync(0xffffffffu, ss, o);

    __shared__ float warp_s[8];
    int wid = threadIdx.x >> 5, lane = threadIdx.x & 31;
    if (lane == 0) warp_s[wid] = ss;
    __syncthreads();
    if (wid == 0) {
        float t = (lane < 8) ? warp_s[lane] : 0.f;
        #pragma unroll
        for (int o = 4; o > 0; o >>= 1)
            t += __shfl_xor_sync(0xffffffffu, t, o);
        if (lane == 0) warp_s[0] = t;
    }
    __syncthreads();
    float sumsq = warp_s[0];
    float rms = sqrtf(sumsq * (1.0f / DIM));
    float inv = 1.0f / (rms + EPS);

    or_[threadIdx.x]       = gamma[threadIdx.x]       * v0 * inv;
    or_[threadIdx.x + 256] = gamma[threadIdx.x + 256] * v1 * inv;
    or_[threadIdx.x + 512] = gamma[threadIdx.x + 512] * v2 * inv;
}

// ---------------- GEMM: C[M,N] = A[M,K] * B[N,K]^T + bias (+resid) ----------
template<bool RESID>
__global__ __launch_bounds__(256)
void gemm_nt_kernel(const float* __restrict__ A,
                    const float* __restrict__ Bm,
                    const float* __restrict__ bias,
                    const float* __restrict__ resid,
                    float* __restrict__ Cout,
                    int M, int N, int K)
{
    __shared__ float As[16][128];
    __shared__ float Bs[16][128];

    const int tid = threadIdx.x;
    const int tx = tid & 15;
    const int ty = tid >> 4;
    const int brow = blockIdx.y * 128;
    const int bcol = blockIdx.x * 128;

    float acc[8][8];
    #pragma unroll
    for (int i = 0; i < 8; i++)
        #pragma unroll
        for (int j = 0; j < 8; j++) acc[i][j] = 0.f;

    for (int kt = 0; kt < K; kt += 16) {
        #pragma unroll
        for (int i = 0; i < 2; i++) {
            int f  = tid + i * 256;
            int r  = f >> 2;
            int c4 = (f & 3) * 4;
            float4 va = *(const float4*)&A [(size_t)(brow + r) * K + kt + c4];
            As[c4 + 0][r] = va.x; As[c4 + 1][r] = va.y;
            As[c4 + 2][r] = va.z; As[c4 + 3][r] = va.w;
            float4 vb = *(const float4*)&Bm[(size_t)(bcol + r) * K + kt + c4];
            Bs[c4 + 0][r] = vb.x; Bs[c4 + 1][r] = vb.y;
            Bs[c4 + 2][r] = vb.z; Bs[c4 + 3][r] = vb.w;
        }
        __syncthreads();

        #pragma unroll
        for (int kk = 0; kk < 16; kk++) {
            float a[8], b[8];
            *(float4*)(a)     = *(const float4*)&As[kk][ty * 8];
            *(float4*)(a + 4) = *(const float4*)&As[kk][ty * 8 + 4];
            *(float4*)(b)     = *(const float4*)&Bs[kk][tx * 8];
            *(float4*)(b + 4) = *(const float4*)&Bs[kk][tx * 8 + 4];
            #pragma unroll
            for (int i = 0; i < 8; i++)
                #pragma unroll
                for (int j = 0; j < 8; j++)
                    acc[i][j] = fmaf(a[i], b[j], acc[i][j]);
        }
        __syncthreads();
    }

    #pragma unroll
    for (int i = 0; i < 8; i++) {
        int r = brow + ty * 8 + i;
        #pragma unroll
        for (int j = 0; j < 8; j += 4) {
            int c = bcol + tx * 8 + j;
            float4 bv = *(const float4*)&bias[c];
            float4 o;
            o.x = acc[i][j + 0] + bv.x;
            o.y = acc[i][j + 1] + bv.y;
            o.z = acc[i][j + 2] + bv.z;
            o.w = acc[i][j + 3] + bv.w;
            if (RESID) {
                float4 rv = *(const float4*)&resid[(size_t)r * N + c];
                o.x += rv.x; o.y += rv.y; o.z += rv.z; o.w += rv.w;
            }
            *(float4*)&Cout[(size_t)r * N + c] = o;
        }
    }
}

// ---------------- K1: chunked local scan (conv fused) ------------------------
// one thread per (b, chunk, e): 16 h-states in registers.
__global__ __launch_bounds__(256)
void scan_chunk_kernel(const float* __restrict__ xp,
                       const float* __restrict__ A,
                       const float* __restrict__ Bp,
                       const float* __restrict__ C,
                       const float* __restrict__ convw,
                       float* __restrict__ y,
                       float* __restrict__ hloc)
{
    int tid = blockIdx.x * blockDim.x + threadIdx.x;   // b*NCH*EE + c*EE + e
    int e  = tid % EE;
    int bc = tid / EE;
    int c  = bc % NCH;
    int b  = bc / NCH;

    float sA[DSTATE], sB[DSTATE], sC[DSTATE], h[DSTATE];
    #pragma unroll
    for (int n = 0; n < DSTATE; n++) {
        sA[n] = sigmoidf_(A [e * DSTATE + n]);
        sB[n] = sigmoidf_(Bp[e * DSTATE + n]);
        sC[n] = sigmoidf_(C [e * DSTATE + n]);
        h[n] = 0.f;
    }
    float w0 = convw[e * 4 + 0];
    float w1 = convw[e * 4 + 1];
    float w2 = convw[e * 4 + 2];
    float w3 = convw[e * 4 + 3];

    const int t0 = c * CH;
    const float* xb = xp + (size_t)b * LL * EE + e;
    float xm1 = (t0 >= 1) ? xb[(size_t)(t0 - 1) * EE] : 0.f;
    float xm2 = (t0 >= 2) ? xb[(size_t)(t0 - 2) * EE] : 0.f;
    float xm3 = (t0 >= 3) ? xb[(size_t)(t0 - 3) * EE] : 0.f;

    const float* xq = xb + (size_t)t0 * EE;
    float*       yb = y + ((size_t)b * LL + t0) * EE + e;

    #pragma unroll 4
    for (int t = 0; t < CH; t++) {
        float xv  = xq[(size_t)t * EE];
        float xcv = xv * w3 + xm1 * w2 + xm2 * w1 + xm3 * w0;
        xm3 = xm2; xm2 = xm1; xm1 = xv;

        float a0 = 0.f, a1 = 0.f, a2 = 0.f, a3 = 0.f;
        #pragma unroll
        for (int n = 0; n < DSTATE; n += 4) {
            h[n + 0] = fmaf(sA[n + 0], h[n + 0], sB[n + 0] * xcv);
            h[n + 1] = fmaf(sA[n + 1], h[n + 1], sB[n + 1] * xcv);
            h[n + 2] = fmaf(sA[n + 2], h[n + 2], sB[n + 2] * xcv);
            h[n + 3] = fmaf(sA[n + 3], h[n + 3], sB[n + 3] * xcv);
            a0 = fmaf(sC[n + 0], h[n + 0], a0);
            a1 = fmaf(sC[n + 1], h[n + 1], a1);
            a2 = fmaf(sC[n + 2], h[n + 2], a2);
            a3 = fmaf(sC[n + 3], h[n + 3], a3);
        }
        yb[(size_t)t * EE] = (a0 + a1) + (a2 + a3);
    }

    // final states -> hloc[b][c][n][e]
    float* hp = hloc + (((size_t)b * NCH + c) * DSTATE) * EE + e;
    #pragma unroll
    for (int n = 0; n < DSTATE; n++)
        hp[(size_t)n * EE] = h[n];
}

// ---------------- K2: combine chunk states sequentially ----------------------
// one thread per (b, n, e)
__global__ void chunk_combine_kernel(const float* __restrict__ hloc,
                                     const float* __restrict__ A,
                                     float* __restrict__ hin)
{
    int tid = blockIdx.x * blockDim.x + threadIdx.x;   // b*DSTATE*EE + n*EE + e
    int e  = tid % EE;
    int bn = tid / EE;
    int n  = bn % DSTATE;
    int b  = bn / DSTATE;

    float sA = sigmoidf_(A[e * DSTATE + n]);
    float pw = sA;
    #pragma unroll
    for (int i = 0; i < 7; i++) pw *= pw;              // sA^128

    size_t base = ((size_t)b * NCH * DSTATE + n) * EE + e;
    const size_t cstride = (size_t)DSTATE * EE;

    float h = 0.f;
    #pragma unroll
    for (int c = 0; c < NCH; c++) {
        hin[base + c * cstride] = h;
        h = fmaf(pw, h, hloc[base + c * cstride]);
    }
}

// ---------------- K3: cross-chunk correction ---------------------------------
// one thread per (b, chunk, e): y_t += sum_n sC_n * sA_n^(tl+1) * hin_n
__global__ __launch_bounds__(256)
void scan_correct_kernel(const float* __restrict__ hin,
                         const float* __restrict__ A,
                         const float* __restrict__ C,
                         float* __restrict__ y)
{
    int tid = blockIdx.x * blockDim.x + threadIdx.x;   // b*NCH*EE + c*EE + e
    int e  = tid % EE;
    int bc = tid / EE;
    int c  = bc % NCH;
    int b  = bc / NCH;

    if (c == 0) return;   // hin == 0

    float sA[DSTATE], sC[DSTATE], q[DSTATE];
    const float* hp = hin + (((size_t)b * NCH + c) * DSTATE) * EE + e;
    #pragma unroll
    for (int n = 0; n < DSTATE; n++) {
        sA[n] = sigmoidf_(A[e * DSTATE + n]);
        sC[n] = sigmoidf_(C[e * DSTATE + n]);
        q[n]  = hp[(size_t)n * EE];
    }

    float* yb = y + ((size_t)b * LL + c * CH) * EE + e;

    #pragma unroll 4
    for (int t = 0; t < CH; t++) {
        float a0 = 0.f, a1 = 0.f, a2 = 0.f, a3 = 0.f;
        #pragma unroll
        for (int n = 0; n < DSTATE; n += 4) {
            q[n + 0] *= sA[n + 0];
            q[n + 1] *= sA[n + 1];
            q[n + 2] *= sA[n + 2];
            q[n + 3] *= sA[n + 3];
            a0 = fmaf(sC[n + 0], q[n + 0], a0);
            a1 = fmaf(sC[n + 1], q[n + 1], a1);
            a2 = fmaf(sC[n + 2], q[n + 2], a2);
            a3 = fmaf(sC[n + 3], q[n + 3], a3);
        }
        yb[(size_t)t * EE] += (a0 + a1) + (a2 + a3);
    }
}

// ---------------- launch -----------------------------------------------------
extern "C" void kernel_launch(void* const* d_in, const int* in_sizes, int n_in,
                              void* d_out, int out_size)
{
    const float* x      = (const float*)d_in[0];
    const float* gamma  = (const float*)d_in[1];
    const float* W_in   = (const float*)d_in[2];
    const float* b_in   = (const float*)d_in[3];
    const float* conv_w = (const float*)d_in[4];
    const float* A      = (const float*)d_in[5];
    const float* Bp     = (const float*)d_in[6];
    const float* C      = (const float*)d_in[7];
    const float* W_out  = (const float*)d_in[8];
    const float* b_out  = (const float*)d_in[9];
    float* out = (float*)d_out;

    float *xn, *xp, *y, *hloc, *hin;
    cudaGetSymbolAddress((void**)&xn,   g_xn);
    cudaGetSymbolAddress((void**)&xp,   g_xp);
    cudaGetSymbolAddress((void**)&y,    g_y);
    cudaGetSymbolAddress((void**)&hloc, g_hloc);
    cudaGetSymbolAddress((void**)&hin,  g_hin);

    // 1. rmsnorm
    rmsnorm_kernel<<<BL, 256>>>(x, gamma, xn);

    // 2. in-proj: xp[BL,EE] = xn[BL,DIM] @ W_in[EE,DIM]^T + b_in
    {
        dim3 grid(EE / 128, BL / 128);
        gemm_nt_kernel<false><<<grid, 256>>>(xn, W_in, b_in, nullptr, xp,
                                             BL, EE, DIM);
    }

    // 3. chunked scan (conv fused)
    {
        int threads = BB * NCH * EE;                   // 49152
        scan_chunk_kernel<<<threads / 256, 256>>>(xp, A, Bp, C, conv_w, y, hloc);
    }
    {
        int threads = BB * DSTATE * EE;                // 49152
        chunk_combine_kernel<<<threads / 256, 256>>>(hloc, A, hin);
    }
    {
        int threads = BB * NCH * EE;                   // 49152
        scan_correct_kernel<<<threads / 256, 256>>>(hin, A, C, y);
    }

    // 4. out-proj + residual: out = y @ W_out^T + b_out + x
    {
        dim3 grid(DIM / 128, BL / 128);
        gemm_nt_kernel<true><<<grid, 256>>>(y, W_out, b_out, x, out,
                                            BL, DIM, EE);
    }
}

// round 6
// speedup vs baseline: 1.9061x; 1.5348x over previous
#include <cuda_runtime.h>
#include <cuda_bf16.h>
#include <math.h>
#include <stdint.h>

#define DIM    768
#define DSTATE 16
#define DCONV  4
#define EE     1536          // expand dim
#define BB     2
#define LL     2048
#define BL     (BB*LL)       // 4096
#define EPS    1e-6f

#define CH     64            // chunk length
#define NCH    (LL/CH)       // 32 chunks

// ---------------- scratch (static device arrays; no allocations) -------------
__device__ float          g_xp  [BL * EE];              // after in-proj (fp32)
__device__ float          g_y   [BL * EE];              // K1 local-scan output (fp32)
__device__ float          g_hloc[BB * NCH * DSTATE * EE];
__device__ float          g_hin [BB * NCH * DSTATE * EE];
__device__ __nv_bfloat16  g_xnh [BL * DIM];             // rmsnorm out hi
__device__ __nv_bfloat16  g_xnl [BL * DIM];             // rmsnorm out lo
__device__ __nv_bfloat16  g_winh[EE * DIM];
__device__ __nv_bfloat16  g_winl[EE * DIM];
__device__ __nv_bfloat16  g_wouth[DIM * EE];
__device__ __nv_bfloat16  g_woutl[DIM * EE];
__device__ __nv_bfloat16  g_yh  [BL * EE];              // final scan out hi
__device__ __nv_bfloat16  g_yl  [BL * EE];              // final scan out lo

__device__ __forceinline__ float sigmoidf_(float v) {
    return 1.0f / (1.0f + expf(-v));
}

__device__ __forceinline__ uint32_t smem_u32_(const void* p) {
    uint32_t a;
    asm("{ .reg .u64 t; cvta.to.shared.u64 t, %1; cvt.u32.u64 %0, t; }"
        : "=r"(a) : "l"(p));
    return a;
}

// ---------------- rmsnorm (writes bf16 hi/lo split) --------------------------
__global__ void rmsnorm_kernel(const float* __restrict__ x,
                               const float* __restrict__ gamma,
                               __nv_bfloat16* __restrict__ xnh,
                               __nv_bfloat16* __restrict__ xnl)
{
    const int row = blockIdx.x;
    const float* xr = x + (size_t)row * DIM;

    float v0 = xr[threadIdx.x];
    float v1 = xr[threadIdx.x + 256];
    float v2 = xr[threadIdx.x + 512];
    float ss = v0 * v0 + v1 * v1 + v2 * v2;

    #pragma unroll
    for (int o = 16; o > 0; o >>= 1)
        ss += __shfl_xor_sync(0xffffffffu, ss, o);

    __shared__ float warp_s[8];
    int wid = threadIdx.x >> 5, lane = threadIdx.x & 31;
    if (lane == 0) warp_s[wid] = ss;
    __syncthreads();
    if (wid == 0) {
        float t = (lane < 8) ? warp_s[lane] : 0.f;
        #pragma unroll
        for (int o = 4; o > 0; o >>= 1)
            t += __shfl_xor_sync(0xffffffffu, t, o);
        if (lane == 0) warp_s[0] = t;
    }
    __syncthreads();
    float rms = sqrtf(warp_s[0] * (1.0f / DIM));
    float inv = 1.0f / (rms + EPS);

    #pragma unroll
    for (int k = 0; k < 3; k++) {
        int i = threadIdx.x + k * 256;
        float v = (k == 0) ? v0 : (k == 1) ? v1 : v2;
        float o = gamma[i] * v * inv;
        __nv_bfloat16 h = __float2bfloat16(o);
        xnh[(size_t)row * DIM + i] = h;
        xnl[(size_t)row * DIM + i] = __float2bfloat16(o - __bfloat162float(h));
    }
}

// ---------------- weight conversion fp32 -> bf16 hi/lo -----------------------
__global__ void convert_w_kernel(const float* __restrict__ W_in,
                                 const float* __restrict__ W_out,
                                 __nv_bfloat16* __restrict__ winh,
                                 __nv_bfloat16* __restrict__ winl,
                                 __nv_bfloat16* __restrict__ wouth,
                                 __nv_bfloat16* __restrict__ woutl)
{
    const int SZ = EE * DIM;
    int idx = blockIdx.x * blockDim.x + threadIdx.x;
    if (idx >= 2 * SZ) return;
    const float* s; __nv_bfloat16 *dh, *dl; int j;
    if (idx < SZ) { s = W_in;  j = idx;      dh = winh;  dl = winl;  }
    else          { s = W_out; j = idx - SZ; dh = wouth; dl = woutl; }
    float v = s[j];
    __nv_bfloat16 h = __float2bfloat16(v);
    dh[j] = h;
    dl[j] = __float2bfloat16(v - __bfloat162float(h));
}

// ======================= HMMA (mma.sync) GEMM ================================
// C[M,N] = A[M,K] * B[N,K]^T + bias (+resid), A/B given as bf16 hi/lo pairs;
// 3 products: Ah*Bh + Ah*Bl + Al*Bh (fp32 accumulate).
// CTA tile 128x128x16, 256 threads, 8 warps (2x4), warp tile 64x32.
// Static shared only (40 KB) -> no cudaFuncSetAttribute needed.

#define BKT   16
#define PADR  20                       // row stride in bf16 units (16 + 4 pad)
#define PLANE (128 * PADR)             // 2560 bf16 per plane
#define STAGE (4 * PLANE)              // Ah, Al, Bh, Bl -> 10240 bf16

__device__ __forceinline__ void mma16816(float* d, const uint32_t* a, const uint32_t* b) {
    asm volatile(
        "mma.sync.aligned.m16n8k16.row.col.f32.bf16.bf16.f32 "
        "{%0,%1,%2,%3}, {%4,%5,%6,%7}, {%8,%9}, {%0,%1,%2,%3};"
        : "+f"(d[0]), "+f"(d[1]), "+f"(d[2]), "+f"(d[3])
        : "r"(a[0]), "r"(a[1]), "r"(a[2]), "r"(a[3]), "r"(b[0]), "r"(b[1]));
}

#define CP_ASYNC8(s, g) asm volatile("cp.async.ca.shared.global [%0], [%1], 8;" :: "r"(s), "l"(g))
#define CP_COMMIT()     asm volatile("cp.async.commit_group;")
#define CP_WAIT1()      asm volatile("cp.async.wait_group 1;")

template<bool RESID>
__global__ __launch_bounds__(256)
void gemm_mma_kernel(const __nv_bfloat16* __restrict__ Ah,
                     const __nv_bfloat16* __restrict__ Al,
                     const __nv_bfloat16* __restrict__ Bh,
                     const __nv_bfloat16* __restrict__ Bl,
                     const float* __restrict__ bias,
                     const float* __restrict__ resid,
                     float* __restrict__ Cout,
                     int N, int K)
{
    __shared__ __nv_bfloat16 sm[2 * STAGE];     // 40960 bytes, static
    const uint32_t sm32 = smem_u32_(sm);
    const int tid  = threadIdx.x;
    const int wid  = tid >> 5, lane = tid & 31;
    const int g    = lane >> 2;           // 0..7
    const int t2   = (lane & 3) * 2;      // 0,2,4,6
    const int brow = blockIdx.y * 128, bcol = blockIdx.x * 128;
    const int warp_m = (wid >> 2) * 64;   // 0 or 64
    const int warp_n = (wid & 3) * 32;    // 0,32,64,96

    const __nv_bfloat16* gptr[4] = { Ah, Al, Bh, Bl };

    float acc[4][4][4];
    #pragma unroll
    for (int mt = 0; mt < 4; mt++)
        #pragma unroll
        for (int nt = 0; nt < 4; nt++)
            #pragma unroll
            for (int q = 0; q < 4; q++) acc[mt][nt][q] = 0.f;

    // stage loader: 4 planes x 128 rows x 16 bf16; 2048 8B-chunks, 8/thread
    auto issue = [&](int st, int kt) {
        uint32_t sb = sm32 + (uint32_t)st * STAGE * 2;
        #pragma unroll
        for (int q = 0; q < 8; q++) {
            int ch = tid + q * 256;              // 0..2047
            int p  = ch >> 9;                    // plane 0..3
            int rc = ch & 511;
            int r  = rc >> 2;                    // row 0..127
            int c  = (rc & 3) * 4;               // bf16 col 0,4,8,12
            int rbase = (p < 2) ? brow : bcol;
            uint32_t sa = sb + (uint32_t)(p * PLANE + r * PADR + c) * 2;
            const __nv_bfloat16* ga = gptr[p] + (size_t)(rbase + r) * K + kt + c;
            CP_ASYNC8(sa, ga);
        }
        CP_COMMIT();
    };

    const int NK = K / BKT;
    issue(0, 0);
    issue(1, BKT);
    CP_WAIT1();
    __syncthreads();

    for (int i = 0; i < NK; i++) {
        const int st = i & 1;
        const __nv_bfloat16* ss = sm + st * STAGE;
        const __nv_bfloat16* pAh = ss;
        const __nv_bfloat16* pAl = ss + PLANE;
        const __nv_bfloat16* pBh = ss + 2 * PLANE;
        const __nv_bfloat16* pBl = ss + 3 * PLANE;

        uint32_t ah[4][4], al[4][4], bh[4][2], bl[4][2];
        #pragma unroll
        for (int mt = 0; mt < 4; mt++) {
            int r0 = warp_m + mt * 16 + g;
            ah[mt][0] = *(const uint32_t*)&pAh[(r0    ) * PADR + t2];
            ah[mt][1] = *(const uint32_t*)&pAh[(r0 + 8) * PADR + t2];
            ah[mt][2] = *(const uint32_t*)&pAh[(r0    ) * PADR + t2 + 8];
            ah[mt][3] = *(const uint32_t*)&pAh[(r0 + 8) * PADR + t2 + 8];
            al[mt][0] = *(const uint32_t*)&pAl[(r0    ) * PADR + t2];
            al[mt][1] = *(const uint32_t*)&pAl[(r0 + 8) * PADR + t2];
            al[mt][2] = *(const uint32_t*)&pAl[(r0    ) * PADR + t2 + 8];
            al[mt][3] = *(const uint32_t*)&pAl[(r0 + 8) * PADR + t2 + 8];
        }
        #pragma unroll
        for (int nt = 0; nt < 4; nt++) {
            int c0 = warp_n + nt * 8 + g;
            bh[nt][0] = *(const uint32_t*)&pBh[c0 * PADR + t2];
            bh[nt][1] = *(const uint32_t*)&pBh[c0 * PADR + t2 + 8];
            bl[nt][0] = *(const uint32_t*)&pBl[c0 * PADR + t2];
            bl[nt][1] = *(const uint32_t*)&pBl[c0 * PADR + t2 + 8];
        }
        #pragma unroll
        for (int mt = 0; mt < 4; mt++)
            #pragma unroll
            for (int nt = 0; nt < 4; nt++) {
                mma16816(acc[mt][nt], ah[mt], bh[nt]);
                mma16816(acc[mt][nt], ah[mt], bl[nt]);
                mma16816(acc[mt][nt], al[mt], bh[nt]);
            }

        __syncthreads();
        if (i + 2 < NK) issue(st, (i + 2) * BKT);
        else            CP_COMMIT();
        CP_WAIT1();
        __syncthreads();
    }

    // -------- epilogue -------------------------------------------------------
    #pragma unroll
    for (int mt = 0; mt < 4; mt++) {
        int r0 = brow + warp_m + mt * 16 + g;
        #pragma unroll
        for (int nt = 0; nt < 4; nt++) {
            int c = bcol + warp_n + nt * 8 + t2;
            float2 bv = *(const float2*)&bias[c];
            float2 o0, o1;
            o0.x = acc[mt][nt][0] + bv.x;
            o0.y = acc[mt][nt][1] + bv.y;
            o1.x = acc[mt][nt][2] + bv.x;
            o1.y = acc[mt][nt][3] + bv.y;
            if (RESID) {
                float2 rv0 = *(const float2*)&resid[(size_t)r0 * N + c];
                float2 rv1 = *(const float2*)&resid[(size_t)(r0 + 8) * N + c];
                o0.x += rv0.x; o0.y += rv0.y;
                o1.x += rv1.x; o1.y += rv1.y;
            }
            *(float2*)&Cout[(size_t)r0 * N + c]       = o0;
            *(float2*)&Cout[(size_t)(r0 + 8) * N + c] = o1;
        }
    }
}

// ---------------- K1: chunked local scan (conv fused) ------------------------
__global__ __launch_bounds__(256)
void scan_chunk_kernel(const float* __restrict__ xp,
                       const float* __restrict__ A,
                       const float* __restrict__ Bp,
                       const float* __restrict__ C,
                       const float* __restrict__ convw,
                       float* __restrict__ y,
                       float* __restrict__ hloc)
{
    int tid = blockIdx.x * blockDim.x + threadIdx.x;   // b*NCH*EE + c*EE + e
    int e  = tid % EE;
    int bc = tid / EE;
    int c  = bc % NCH;
    int b  = bc / NCH;

    float sA[DSTATE], sB[DSTATE], sC[DSTATE], h[DSTATE];
    #pragma unroll
    for (int n = 0; n < DSTATE; n++) {
        sA[n] = sigmoidf_(A [e * DSTATE + n]);
        sB[n] = sigmoidf_(Bp[e * DSTATE + n]);
        sC[n] = sigmoidf_(C [e * DSTATE + n]);
        h[n] = 0.f;
    }
    float w0 = convw[e * 4 + 0];
    float w1 = convw[e * 4 + 1];
    float w2 = convw[e * 4 + 2];
    float w3 = convw[e * 4 + 3];

    const int t0 = c * CH;
    const float* xb = xp + (size_t)b * LL * EE + e;
    float xm1 = (t0 >= 1) ? xb[(size_t)(t0 - 1) * EE] : 0.f;
    float xm2 = (t0 >= 2) ? xb[(size_t)(t0 - 2) * EE] : 0.f;
    float xm3 = (t0 >= 3) ? xb[(size_t)(t0 - 3) * EE] : 0.f;

    const float* xq = xb + (size_t)t0 * EE;
    float*       yb = y + ((size_t)b * LL + t0) * EE + e;

    #pragma unroll 4
    for (int t = 0; t < CH; t++) {
        float xv  = xq[(size_t)t * EE];
        float xcv = xv * w3 + xm1 * w2 + xm2 * w1 + xm3 * w0;
        xm3 = xm2; xm2 = xm1; xm1 = xv;

        float a0 = 0.f, a1 = 0.f, a2 = 0.f, a3 = 0.f;
        #pragma unroll
        for (int n = 0; n < DSTATE; n += 4) {
            h[n + 0] = fmaf(sA[n + 0], h[n + 0], sB[n + 0] * xcv);
            h[n + 1] = fmaf(sA[n + 1], h[n + 1], sB[n + 1] * xcv);
            h[n + 2] = fmaf(sA[n + 2], h[n + 2], sB[n + 2] * xcv);
            h[n + 3] = fmaf(sA[n + 3], h[n + 3], sB[n + 3] * xcv);
            a0 = fmaf(sC[n + 0], h[n + 0], a0);
            a1 = fmaf(sC[n + 1], h[n + 1], a1);
            a2 = fmaf(sC[n + 2], h[n + 2], a2);
            a3 = fmaf(sC[n + 3], h[n + 3], a3);
        }
        yb[(size_t)t * EE] = (a0 + a1) + (a2 + a3);
    }

    float* hp = hloc + (((size_t)b * NCH + c) * DSTATE) * EE + e;
    #pragma unroll
    for (int n = 0; n < DSTATE; n++)
        hp[(size_t)n * EE] = h[n];
}

// ---------------- K2: combine chunk states sequentially ----------------------
__global__ void chunk_combine_kernel(const float* __restrict__ hloc,
                                     const float* __restrict__ A,
                                     float* __restrict__ hin)
{
    int tid = blockIdx.x * blockDim.x + threadIdx.x;   // b*DSTATE*EE + n*EE + e
    int e  = tid % EE;
    int bn = tid / EE;
    int n  = bn % DSTATE;
    int b  = bn / DSTATE;

    float sA = sigmoidf_(A[e * DSTATE + n]);
    float pw = sA;
    #pragma unroll
    for (int i = 0; i < 6; i++) pw *= pw;              // sA^64 (CH=64)

    size_t base = ((size_t)b * NCH * DSTATE + n) * EE + e;
    const size_t cstride = (size_t)DSTATE * EE;

    float h = 0.f;
    #pragma unroll
    for (int c = 0; c < NCH; c++) {
        hin[base + c * cstride] = h;
        h = fmaf(pw, h, hloc[base + c * cstride]);
    }
}

// ---------------- K3: cross-chunk correction + bf16 split output -------------
__global__ __launch_bounds__(256)
void scan_correct_kernel(const float* __restrict__ hin,
                         const float* __restrict__ A,
                         const float* __restrict__ C,
                         const float* __restrict__ y,
                         __nv_bfloat16* __restrict__ yh,
                         __nv_bfloat16* __restrict__ yl)
{
    int tid = blockIdx.x * blockDim.x + threadIdx.x;   // b*NCH*EE + c*EE + e
    int e  = tid % EE;
    int bc = tid / EE;
    int c  = bc % NCH;
    int b  = bc / NCH;

    float sA[DSTATE], sC[DSTATE], q[DSTATE];
    const float* hp = hin + (((size_t)b * NCH + c) * DSTATE) * EE + e;
    #pragma unroll
    for (int n = 0; n < DSTATE; n++) {
        sA[n] = sigmoidf_(A[e * DSTATE + n]);
        sC[n] = sigmoidf_(C[e * DSTATE + n]);
        q[n]  = (c > 0) ? hp[(size_t)n * EE] : 0.f;
    }

    size_t base = ((size_t)b * LL + c * CH) * EE + e;
    const float* yb = y + base;
    __nv_bfloat16* yhb = yh + base;
    __nv_bfloat16* ylb = yl + base;

    #pragma unroll 4
    for (int t = 0; t < CH; t++) {
        float a0 = 0.f, a1 = 0.f, a2 = 0.f, a3 = 0.f;
        #pragma unroll
        for (int n = 0; n < DSTATE; n += 4) {
            q[n + 0] *= sA[n + 0];
            q[n + 1] *= sA[n + 1];
            q[n + 2] *= sA[n + 2];
            q[n + 3] *= sA[n + 3];
            a0 = fmaf(sC[n + 0], q[n + 0], a0);
            a1 = fmaf(sC[n + 1], q[n + 1], a1);
            a2 = fmaf(sC[n + 2], q[n + 2], a2);
            a3 = fmaf(sC[n + 3], q[n + 3], a3);
        }
        float v = yb[(size_t)t * EE] + (a0 + a1) + (a2 + a3);
        __nv_bfloat16 hv = __float2bfloat16(v);
        yhb[(size_t)t * EE] = hv;
        ylb[(size_t)t * EE] = __float2bfloat16(v - __bfloat162float(hv));
    }
}

// ---------------- launch -----------------------------------------------------
extern "C" void kernel_launch(void* const* d_in, const int* in_sizes, int n_in,
                              void* d_out, int out_size)
{
    const float* x      = (const float*)d_in[0];
    const float* gamma  = (const float*)d_in[1];
    const float* W_in   = (const float*)d_in[2];
    const float* b_in   = (const float*)d_in[3];
    const float* conv_w = (const float*)d_in[4];
    const float* A      = (const float*)d_in[5];
    const float* Bp     = (const float*)d_in[6];
    const float* C      = (const float*)d_in[7];
    const float* W_out  = (const float*)d_in[8];
    const float* b_out  = (const float*)d_in[9];
    float* out = (float*)d_out;

    float *xp, *y, *hloc, *hin;
    __nv_bfloat16 *xnh, *xnl, *winh, *winl, *wouth, *woutl, *yh, *yl;
    cudaGetSymbolAddress((void**)&xp,    g_xp);
    cudaGetSymbolAddress((void**)&y,     g_y);
    cudaGetSymbolAddress((void**)&hloc,  g_hloc);
    cudaGetSymbolAddress((void**)&hin,   g_hin);
    cudaGetSymbolAddress((void**)&xnh,   g_xnh);
    cudaGetSymbolAddress((void**)&xnl,   g_xnl);
    cudaGetSymbolAddress((void**)&winh,  g_winh);
    cudaGetSymbolAddress((void**)&winl,  g_winl);
    cudaGetSymbolAddress((void**)&wouth, g_wouth);
    cudaGetSymbolAddress((void**)&woutl, g_woutl);
    cudaGetSymbolAddress((void**)&yh,    g_yh);
    cudaGetSymbolAddress((void**)&yl,    g_yl);

    // 1. rmsnorm -> bf16 hi/lo
    rmsnorm_kernel<<<BL, 256>>>(x, gamma, xnh, xnl);

    // 1b. convert weights -> bf16 hi/lo
    convert_w_kernel<<<(2 * EE * DIM + 255) / 256, 256>>>(W_in, W_out,
                                                          winh, winl, wouth, woutl);

    // 2. in-proj (HMMA): xp = xn @ W_in^T + b_in
    {
        dim3 grid(EE / 128, BL / 128);
        gemm_mma_kernel<false><<<grid, 256>>>(xnh, xnl, winh, winl,
                                              b_in, nullptr, xp, EE, DIM);
    }

    // 3. chunked scan (conv fused)
    {
        int threads = BB * NCH * EE;                   // 98304
        scan_chunk_kernel<<<threads / 256, 256>>>(xp, A, Bp, C, conv_w, y, hloc);
    }
    {
        int threads = BB * DSTATE * EE;                // 49152
        chunk_combine_kernel<<<threads / 256, 256>>>(hloc, A, hin);
    }
    {
        int threads = BB * NCH * EE;
        scan_correct_kernel<<<threads / 256, 256>>>(hin, A, C, y, yh, yl);
    }

    // 4. out-proj + residual (HMMA): out = y @ W_out^T + b_out + x
    {
        dim3 grid(DIM / 128, BL / 128);
        gemm_mma_kernel<true><<<grid, 256>>>(yh, yl, wouth, woutl,
                                             b_out, x, out, DIM, EE);
    }
}

// round 7
// speedup vs baseline: 2.4743x; 1.2981x over previous
#include <cuda_runtime.h>
#include <cuda_bf16.h>
#include <math.h>
#include <stdint.h>

#define DIM    768
#define DSTATE 16
#define DCONV  4
#define EE     1536          // expand dim
#define BB     2
#define LL     2048
#define BL     (BB*LL)       // 4096
#define EPS    1e-6f

#define CH     32            // chunk length
#define NCH    (LL/CH)       // 64 chunks

// ---------------- scratch (static device arrays; no allocations) -------------
__device__ float          g_xp  [BL * EE];              // after in-proj (fp32)
__device__ float          g_y   [BL * EE];              // K1 local-scan output (fp32)
__device__ float          g_hloc[BB * NCH * DSTATE * EE];
__device__ float          g_hin [BB * NCH * DSTATE * EE];
__device__ __nv_bfloat16  g_xnh [BL * DIM];             // rmsnorm out hi
__device__ __nv_bfloat16  g_xnl [BL * DIM];             // rmsnorm out lo
__device__ __nv_bfloat16  g_winh[EE * DIM];
__device__ __nv_bfloat16  g_winl[EE * DIM];
__device__ __nv_bfloat16  g_wouth[DIM * EE];
__device__ __nv_bfloat16  g_woutl[DIM * EE];
__device__ __nv_bfloat16  g_yh  [BL * EE];              // final scan out hi
__device__ __nv_bfloat16  g_yl  [BL * EE];              // final scan out lo

__device__ __forceinline__ float sigmoidf_(float v) {
    return 1.0f / (1.0f + expf(-v));
}

__device__ __forceinline__ uint32_t smem_u32_(const void* p) {
    uint32_t a;
    asm("{ .reg .u64 t; cvta.to.shared.u64 t, %1; cvt.u32.u64 %0, t; }"
        : "=r"(a) : "l"(p));
    return a;
}

// ---------------- rmsnorm (writes bf16 hi/lo split) --------------------------
__global__ void rmsnorm_kernel(const float* __restrict__ x,
                               const float* __restrict__ gamma,
                               __nv_bfloat16* __restrict__ xnh,
                               __nv_bfloat16* __restrict__ xnl)
{
    const int row = blockIdx.x;
    const float* xr = x + (size_t)row * DIM;

    float v0 = xr[threadIdx.x];
    float v1 = xr[threadIdx.x + 256];
    float v2 = xr[threadIdx.x + 512];
    float ss = v0 * v0 + v1 * v1 + v2 * v2;

    #pragma unroll
    for (int o = 16; o > 0; o >>= 1)
        ss += __shfl_xor_sync(0xffffffffu, ss, o);

    __shared__ float warp_s[8];
    int wid = threadIdx.x >> 5, lane = threadIdx.x & 31;
    if (lane == 0) warp_s[wid] = ss;
    __syncthreads();
    if (wid == 0) {
        float t = (lane < 8) ? warp_s[lane] : 0.f;
        #pragma unroll
        for (int o = 4; o > 0; o >>= 1)
            t += __shfl_xor_sync(0xffffffffu, t, o);
        if (lane == 0) warp_s[0] = t;
    }
    __syncthreads();
    float rms = sqrtf(warp_s[0] * (1.0f / DIM));
    float inv = 1.0f / (rms + EPS);

    #pragma unroll
    for (int k = 0; k < 3; k++) {
        int i = threadIdx.x + k * 256;
        float v = (k == 0) ? v0 : (k == 1) ? v1 : v2;
        float o = gamma[i] * v * inv;
        __nv_bfloat16 h = __float2bfloat16(o);
        xnh[(size_t)row * DIM + i] = h;
        xnl[(size_t)row * DIM + i] = __float2bfloat16(o - __bfloat162float(h));
    }
}

// ---------------- weight conversion fp32 -> bf16 hi/lo -----------------------
__global__ void convert_w_kernel(const float* __restrict__ W_in,
                                 const float* __restrict__ W_out,
                                 __nv_bfloat16* __restrict__ winh,
                                 __nv_bfloat16* __restrict__ winl,
                                 __nv_bfloat16* __restrict__ wouth,
                                 __nv_bfloat16* __restrict__ woutl)
{
    const int SZ = EE * DIM;
    int idx = blockIdx.x * blockDim.x + threadIdx.x;
    if (idx >= 2 * SZ) return;
    const float* s; __nv_bfloat16 *dh, *dl; int j;
    if (idx < SZ) { s = W_in;  j = idx;      dh = winh;  dl = winl;  }
    else          { s = W_out; j = idx - SZ; dh = wouth; dl = woutl; }
    float v = s[j];
    __nv_bfloat16 h = __float2bfloat16(v);
    dh[j] = h;
    dl[j] = __float2bfloat16(v - __bfloat162float(h));
}

// ======================= HMMA (mma.sync) GEMM ================================
// C[M,N] = A[M,K] * B[N,K]^T + bias (+resid), A/B given as bf16 hi/lo pairs;
// 3 products: Ah*Bh + Ah*Bl + Al*Bh (fp32 accumulate).
// CTA tile 128x128x16, 256 threads, 8 warps (2x4), warp tile 64x32.
// ldmatrix.x4 fragment loads; static shared 48KB exactly, no attribute calls.

#define BKT   16
#define PADR  24                       // bf16 per row (16 data + 8 pad) -> 48B rows
#define PLANE (128 * PADR)             // 3072 bf16 per plane
#define STAGE (4 * PLANE)              // Ah, Al, Bh, Bl -> 12288 bf16 (24KB)

__device__ __forceinline__ void mma16816(float* d, const uint32_t* a, const uint32_t* b) {
    asm volatile(
        "mma.sync.aligned.m16n8k16.row.col.f32.bf16.bf16.f32 "
        "{%0,%1,%2,%3}, {%4,%5,%6,%7}, {%8,%9}, {%0,%1,%2,%3};"
        : "+f"(d[0]), "+f"(d[1]), "+f"(d[2]), "+f"(d[3])
        : "r"(a[0]), "r"(a[1]), "r"(a[2]), "r"(a[3]), "r"(b[0]), "r"(b[1]));
}

__device__ __forceinline__ void ldsm4(uint32_t* r, uint32_t addr) {
    asm volatile("ldmatrix.sync.aligned.m8n8.x4.shared.b16 {%0,%1,%2,%3}, [%4];"
                 : "=r"(r[0]), "=r"(r[1]), "=r"(r[2]), "=r"(r[3]) : "r"(addr));
}

#define CP_ASYNC8(s, g) asm volatile("cp.async.ca.shared.global [%0], [%1], 8;" :: "r"(s), "l"(g))
#define CP_COMMIT()     asm volatile("cp.async.commit_group;")
#define CP_WAIT1()      asm volatile("cp.async.wait_group 1;")

template<bool RESID>
__global__ __launch_bounds__(256)
void gemm_mma_kernel(const __nv_bfloat16* __restrict__ Ah,
                     const __nv_bfloat16* __restrict__ Al,
                     const __nv_bfloat16* __restrict__ Bh,
                     const __nv_bfloat16* __restrict__ Bl,
                     const float* __restrict__ bias,
                     const float* __restrict__ resid,
                     float* __restrict__ Cout,
                     int N, int K)
{
    __shared__ __nv_bfloat16 sm[2 * STAGE];     // 49152 bytes, static
    const uint32_t sm32 = smem_u32_(sm);
    const int tid  = threadIdx.x;
    const int wid  = tid >> 5, lane = tid & 31;
    const int g    = lane >> 2;           // 0..7
    const int t2   = (lane & 3) * 2;      // 0,2,4,6
    const int brow = blockIdx.y * 128, bcol = blockIdx.x * 128;
    const int warp_m = (wid >> 2) * 64;   // 0 or 64
    const int warp_n = (wid & 3) * 32;    // 0,32,64,96

    const __nv_bfloat16* gptr[4] = { Ah, Al, Bh, Bl };

    // per-lane ldmatrix byte offsets (within a plane)
    const int arow  = (lane & 7) + 8 * ((lane >> 3) & 1);
    const int akofs = 8 * (lane >> 4);
    const uint32_t a_off = (uint32_t)((warp_m + arow) * PADR + akofs) * 2;  // + mt*16*PADR*2
    const int browl = (lane & 7) + 8 * (lane >> 4);
    const int bkofs = 8 * ((lane >> 3) & 1);
    const uint32_t b_off = (uint32_t)((warp_n + browl) * PADR + bkofs) * 2; // + ntp*16*PADR*2

    float acc[4][4][4];
    #pragma unroll
    for (int mt = 0; mt < 4; mt++)
        #pragma unroll
        for (int nt = 0; nt < 4; nt++)
            #pragma unroll
            for (int q = 0; q < 4; q++) acc[mt][nt][q] = 0.f;

    // stage loader: 4 planes x 128 rows x 16 bf16; 2048 8B-chunks, 8/thread
    auto issue = [&](int st, int kt) {
        uint32_t sb = sm32 + (uint32_t)st * STAGE * 2;
        #pragma unroll
        for (int q = 0; q < 8; q++) {
            int ch = tid + q * 256;              // 0..2047
            int p  = ch >> 9;                    // plane 0..3
            int rc = ch & 511;
            int r  = rc >> 2;                    // row 0..127
            int c  = (rc & 3) * 4;               // bf16 col 0,4,8,12
            int rbase = (p < 2) ? brow : bcol;
            uint32_t sa = sb + (uint32_t)(p * PLANE + r * PADR + c) * 2;
            const __nv_bfloat16* ga = gptr[p] + (size_t)(rbase + r) * K + kt + c;
            CP_ASYNC8(sa, ga);
        }
        CP_COMMIT();
    };

    const int NK = K / BKT;
    issue(0, 0);
    issue(1, BKT);
    CP_WAIT1();
    __syncthreads();

    for (int i = 0; i < NK; i++) {
        const int st = i & 1;
        const uint32_t sbase = sm32 + (uint32_t)st * STAGE * 2;

        uint32_t ah[4][4], al[4][4], bh[2][4], bl[2][4];
        #pragma unroll
        for (int mt = 0; mt < 4; mt++) {
            uint32_t ad = sbase + a_off + (uint32_t)(mt * 16 * PADR) * 2;
            ldsm4(ah[mt], ad);
            ldsm4(al[mt], ad + (uint32_t)PLANE * 2);
        }
        #pragma unroll
        for (int ntp = 0; ntp < 2; ntp++) {
            uint32_t bd = sbase + b_off + (uint32_t)((2 * PLANE) + ntp * 16 * PADR) * 2;
            ldsm4(bh[ntp], bd);
            ldsm4(bl[ntp], bd + (uint32_t)PLANE * 2);
        }

        #pragma unroll
        for (int mt = 0; mt < 4; mt++)
            #pragma unroll
            for (int nt = 0; nt < 4; nt++) {
                const uint32_t* fh = &bh[nt >> 1][(nt & 1) * 2];
                const uint32_t* fl = &bl[nt >> 1][(nt & 1) * 2];
                mma16816(acc[mt][nt], ah[mt], fh);
                mma16816(acc[mt][nt], ah[mt], fl);
                mma16816(acc[mt][nt], al[mt], fh);
            }

        __syncthreads();
        if (i + 2 < NK) issue(st, (i + 2) * BKT);
        else            CP_COMMIT();
        CP_WAIT1();
        __syncthreads();
    }

    // -------- epilogue -------------------------------------------------------
    #pragma unroll
    for (int mt = 0; mt < 4; mt++) {
        int r0 = brow + warp_m + mt * 16 + g;
        #pragma unroll
        for (int nt = 0; nt < 4; nt++) {
            int c = bcol + warp_n + nt * 8 + t2;
            float2 bv = *(const float2*)&bias[c];
            float2 o0, o1;
            o0.x = acc[mt][nt][0] + bv.x;
            o0.y = acc[mt][nt][1] + bv.y;
            o1.x = acc[mt][nt][2] + bv.x;
            o1.y = acc[mt][nt][3] + bv.y;
            if (RESID) {
                float2 rv0 = *(const float2*)&resid[(size_t)r0 * N + c];
                float2 rv1 = *(const float2*)&resid[(size_t)(r0 + 8) * N + c];
                o0.x += rv0.x; o0.y += rv0.y;
                o1.x += rv1.x; o1.y += rv1.y;
            }
            *(float2*)&Cout[(size_t)r0 * N + c]       = o0;
            *(float2*)&Cout[(size_t)(r0 + 8) * N + c] = o1;
        }
    }
}

// ---------------- K1: chunked local scan (conv fused, batched loads) ---------
__global__ __launch_bounds__(256)
void scan_chunk_kernel(const float* __restrict__ xp,
                       const float* __restrict__ A,
                       const float* __restrict__ Bp,
                       const float* __restrict__ C,
                       const float* __restrict__ convw,
                       float* __restrict__ y,
                       float* __restrict__ hloc)
{
    int tid = blockIdx.x * blockDim.x + threadIdx.x;   // b*NCH*EE + c*EE + e
    int e  = tid % EE;
    int bc = tid / EE;
    int c  = bc % NCH;
    int b  = bc / NCH;

    float sA[DSTATE], sB[DSTATE], sC[DSTATE], h[DSTATE];
    #pragma unroll
    for (int n = 0; n < DSTATE; n++) {
        sA[n] = sigmoidf_(A [e * DSTATE + n]);
        sB[n] = sigmoidf_(Bp[e * DSTATE + n]);
        sC[n] = sigmoidf_(C [e * DSTATE + n]);
        h[n] = 0.f;
    }
    float w0 = convw[e * 4 + 0];
    float w1 = convw[e * 4 + 1];
    float w2 = convw[e * 4 + 2];
    float w3 = convw[e * 4 + 3];

    const int t0 = c * CH;
    const float* xb = xp + (size_t)b * LL * EE + e;
    float xm1 = (t0 >= 1) ? xb[(size_t)(t0 - 1) * EE] : 0.f;
    float xm2 = (t0 >= 2) ? xb[(size_t)(t0 - 2) * EE] : 0.f;
    float xm3 = (t0 >= 3) ? xb[(size_t)(t0 - 3) * EE] : 0.f;

    const float* xq = xb + (size_t)t0 * EE;
    float*       yb = y + ((size_t)b * LL + t0) * EE + e;

    #pragma unroll
    for (int tb = 0; tb < CH; tb += 8) {
        float xv[8];
        #pragma unroll
        for (int j = 0; j < 8; j++)
            xv[j] = xq[(size_t)(tb + j) * EE];

        #pragma unroll
        for (int j = 0; j < 8; j++) {
            float xcv = xv[j] * w3 + xm1 * w2 + xm2 * w1 + xm3 * w0;
            xm3 = xm2; xm2 = xm1; xm1 = xv[j];

            float a0 = 0.f, a1 = 0.f, a2 = 0.f, a3 = 0.f;
            #pragma unroll
            for (int n = 0; n < DSTATE; n += 4) {
                h[n + 0] = fmaf(sA[n + 0], h[n + 0], sB[n + 0] * xcv);
                h[n + 1] = fmaf(sA[n + 1], h[n + 1], sB[n + 1] * xcv);
                h[n + 2] = fmaf(sA[n + 2], h[n + 2], sB[n + 2] * xcv);
                h[n + 3] = fmaf(sA[n + 3], h[n + 3], sB[n + 3] * xcv);
                a0 = fmaf(sC[n + 0], h[n + 0], a0);
                a1 = fmaf(sC[n + 1], h[n + 1], a1);
                a2 = fmaf(sC[n + 2], h[n + 2], a2);
                a3 = fmaf(sC[n + 3], h[n + 3], a3);
            }
            yb[(size_t)(tb + j) * EE] = (a0 + a1) + (a2 + a3);
        }
    }

    float* hp = hloc + (((size_t)b * NCH + c) * DSTATE) * EE + e;
    #pragma unroll
    for (int n = 0; n < DSTATE; n++)
        hp[(size_t)n * EE] = h[n];
}

// ---------------- K2: combine chunk states sequentially ----------------------
__global__ void chunk_combine_kernel(const float* __restrict__ hloc,
                                     const float* __restrict__ A,
                                     float* __restrict__ hin)
{
    int tid = blockIdx.x * blockDim.x + threadIdx.x;   // b*DSTATE*EE + n*EE + e
    int e  = tid % EE;
    int bn = tid / EE;
    int n  = bn % DSTATE;
    int b  = bn / DSTATE;

    float sA = sigmoidf_(A[e * DSTATE + n]);
    float pw = sA;
    #pragma unroll
    for (int i = 0; i < 5; i++) pw *= pw;              // sA^32 (CH=32)

    size_t base = ((size_t)b * NCH * DSTATE + n) * EE + e;
    const size_t cstride = (size_t)DSTATE * EE;

    float h = 0.f;
    #pragma unroll
    for (int c = 0; c < NCH; c++) {
        hin[base + c * cstride] = h;
        h = fmaf(pw, h, hloc[base + c * cstride]);
    }
}

// ---------------- K3: cross-chunk correction + bf16 split output -------------
__global__ __launch_bounds__(256)
void scan_correct_kernel(const float* __restrict__ hin,
                         const float* __restrict__ A,
                         const float* __restrict__ C,
                         const float* __restrict__ y,
                         __nv_bfloat16* __restrict__ yh,
                         __nv_bfloat16* __restrict__ yl)
{
    int tid = blockIdx.x * blockDim.x + threadIdx.x;   // b*NCH*EE + c*EE + e
    int e  = tid % EE;
    int bc = tid / EE;
    int c  = bc % NCH;
    int b  = bc / NCH;

    float sA[DSTATE], sC[DSTATE], q[DSTATE];
    const float* hp = hin + (((size_t)b * NCH + c) * DSTATE) * EE + e;
    #pragma unroll
    for (int n = 0; n < DSTATE; n++) {
        sA[n] = sigmoidf_(A[e * DSTATE + n]);
        sC[n] = sigmoidf_(C[e * DSTATE + n]);
        q[n]  = (c > 0) ? hp[(size_t)n * EE] : 0.f;
    }

    size_t base = ((size_t)b * LL + c * CH) * EE + e;
    const float* yb = y + base;
    __nv_bfloat16* yhb = yh + base;
    __nv_bfloat16* ylb = yl + base;

    #pragma unroll
    for (int tb = 0; tb < CH; tb += 8) {
        float yv[8];
        #pragma unroll
        for (int j = 0; j < 8; j++)
            yv[j] = yb[(size_t)(tb + j) * EE];

        #pragma unroll
        for (int j = 0; j < 8; j++) {
            float a0 = 0.f, a1 = 0.f, a2 = 0.f, a3 = 0.f;
            #pragma unroll
            for (int n = 0; n < DSTATE; n += 4) {
                q[n + 0] *= sA[n + 0];
                q[n + 1] *= sA[n + 1];
                q[n + 2] *= sA[n + 2];
                q[n + 3] *= sA[n + 3];
                a0 = fmaf(sC[n + 0], q[n + 0], a0);
                a1 = fmaf(sC[n + 1], q[n + 1], a1);
                a2 = fmaf(sC[n + 2], q[n + 2], a2);
                a3 = fmaf(sC[n + 3], q[n + 3], a3);
            }
            float v = yv[j] + (a0 + a1) + (a2 + a3);
            __nv_bfloat16 hv = __float2bfloat16(v);
            yhb[(size_t)(tb + j) * EE] = hv;
            ylb[(size_t)(tb + j) * EE] = __float2bfloat16(v - __bfloat162float(hv));
        }
    }
}

// ---------------- launch -----------------------------------------------------
extern "C" void kernel_launch(void* const* d_in, const int* in_sizes, int n_in,
                              void* d_out, int out_size)
{
    const float* x      = (const float*)d_in[0];
    const float* gamma  = (const float*)d_in[1];
    const float* W_in   = (const float*)d_in[2];
    const float* b_in   = (const float*)d_in[3];
    const float* conv_w = (const float*)d_in[4];
    const float* A      = (const float*)d_in[5];
    const float* Bp     = (const float*)d_in[6];
    const float* C      = (const float*)d_in[7];
    const float* W_out  = (const float*)d_in[8];
    const float* b_out  = (const float*)d_in[9];
    float* out = (float*)d_out;

    float *xp, *y, *hloc, *hin;
    __nv_bfloat16 *xnh, *xnl, *winh, *winl, *wouth, *woutl, *yh, *yl;
    cudaGetSymbolAddress((void**)&xp,    g_xp);
    cudaGetSymbolAddress((void**)&y,     g_y);
    cudaGetSymbolAddress((void**)&hloc,  g_hloc);
    cudaGetSymbolAddress((void**)&hin,   g_hin);
    cudaGetSymbolAddress((void**)&xnh,   g_xnh);
    cudaGetSymbolAddress((void**)&xnl,   g_xnl);
    cudaGetSymbolAddress((void**)&winh,  g_winh);
    cudaGetSymbolAddress((void**)&winl,  g_winl);
    cudaGetSymbolAddress((void**)&wouth, g_wouth);
    cudaGetSymbolAddress((void**)&woutl, g_woutl);
    cudaGetSymbolAddress((void**)&yh,    g_yh);
    cudaGetSymbolAddress((void**)&yl,    g_yl);

    // 1. rmsnorm -> bf16 hi/lo
    rmsnorm_kernel<<<BL, 256>>>(x, gamma, xnh, xnl);

    // 1b. convert weights -> bf16 hi/lo
    convert_w_kernel<<<(2 * EE * DIM + 255) / 256, 256>>>(W_in, W_out,
                                                          winh, winl, wouth, woutl);

    // 2. in-proj (HMMA): xp = xn @ W_in^T + b_in
    {
        dim3 grid(EE / 128, BL / 128);
        gemm_mma_kernel<false><<<grid, 256>>>(xnh, xnl, winh, winl,
                                              b_in, nullptr, xp, EE, DIM);
    }

    // 3. chunked scan (conv fused)
    {
        int threads = BB * NCH * EE;                   // 196608
        scan_chunk_kernel<<<threads / 256, 256>>>(xp, A, Bp, C, conv_w, y, hloc);
    }
    {
        int threads = BB * DSTATE * EE;                // 49152
        chunk_combine_kernel<<<threads / 256, 256>>>(hloc, A, hin);
    }
    {
        int threads = BB * NCH * EE;
        scan_correct_kernel<<<threads / 256, 256>>>(hin, A, C, y, yh, yl);
    }

    // 4. out-proj + residual (HMMA): out = y @ W_out^T + b_out + x
    {
        dim3 grid(DIM / 128, BL / 128);
        gemm_mma_kernel<true><<<grid, 256>>>(yh, yl, wouth, woutl,
                                             b_out, x, out, DIM, EE);
    }
}

// round 8
// speedup vs baseline: 2.4912x; 1.0068x over previous
#include <cuda_runtime.h>
#include <cuda_bf16.h>
#include <math.h>
#include <stdint.h>

#define DIM    768
#define DSTATE 16
#define DCONV  4
#define EE     1536          // expand dim
#define BB     2
#define LL     2048
#define BL     (BB*LL)       // 4096
#define EPS    1e-6f

#define CH     32            // chunk length
#define NCH    (LL/CH)       // 64 chunks

// ---------------- scratch (static device arrays; no allocations) -------------
__device__ float          g_xp  [BL * EE];              // after in-proj (fp32)
__device__ float          g_hloc[BB * NCH * DSTATE * EE];
__device__ float          g_hin [BB * NCH * DSTATE * EE];
__device__ __nv_bfloat16  g_xnh [BL * DIM];             // rmsnorm out hi
__device__ __nv_bfloat16  g_xnl [BL * DIM];             // rmsnorm out lo
__device__ __nv_bfloat16  g_winh[EE * DIM];
__device__ __nv_bfloat16  g_winl[EE * DIM];
__device__ __nv_bfloat16  g_wouth[DIM * EE];
__device__ __nv_bfloat16  g_woutl[DIM * EE];
__device__ __nv_bfloat16  g_yh  [BL * EE];              // final scan out hi
__device__ __nv_bfloat16  g_yl  [BL * EE];              // final scan out lo

__device__ __forceinline__ float sigmoidf_(float v) {
    return 1.0f / (1.0f + expf(-v));
}

__device__ __forceinline__ uint32_t smem_u32_(const void* p) {
    uint32_t a;
    asm("{ .reg .u64 t; cvta.to.shared.u64 t, %1; cvt.u32.u64 %0, t; }"
        : "=r"(a) : "l"(p));
    return a;
}

// ---------------- rmsnorm (writes bf16 hi/lo split) --------------------------
__global__ void rmsnorm_kernel(const float* __restrict__ x,
                               const float* __restrict__ gamma,
                               __nv_bfloat16* __restrict__ xnh,
                               __nv_bfloat16* __restrict__ xnl)
{
    const int row = blockIdx.x;
    const float* xr = x + (size_t)row * DIM;

    float v0 = xr[threadIdx.x];
    float v1 = xr[threadIdx.x + 256];
    float v2 = xr[threadIdx.x + 512];
    float ss = v0 * v0 + v1 * v1 + v2 * v2;

    #pragma unroll
    for (int o = 16; o > 0; o >>= 1)
        ss += __shfl_xor_sync(0xffffffffu, ss, o);

    __shared__ float warp_s[8];
    int wid = threadIdx.x >> 5, lane = threadIdx.x & 31;
    if (lane == 0) warp_s[wid] = ss;
    __syncthreads();
    if (wid == 0) {
        float t = (lane < 8) ? warp_s[lane] : 0.f;
        #pragma unroll
        for (int o = 4; o > 0; o >>= 1)
            t += __shfl_xor_sync(0xffffffffu, t, o);
        if (lane == 0) warp_s[0] = t;
    }
    __syncthreads();
    float rms = sqrtf(warp_s[0] * (1.0f / DIM));
    float inv = 1.0f / (rms + EPS);

    #pragma unroll
    for (int k = 0; k < 3; k++) {
        int i = threadIdx.x + k * 256;
        float v = (k == 0) ? v0 : (k == 1) ? v1 : v2;
        float o = gamma[i] * v * inv;
        __nv_bfloat16 h = __float2bfloat16(o);
        xnh[(size_t)row * DIM + i] = h;
        xnl[(size_t)row * DIM + i] = __float2bfloat16(o - __bfloat162float(h));
    }
}

// ---------------- weight conversion fp32 -> bf16 hi/lo -----------------------
__global__ void convert_w_kernel(const float* __restrict__ W_in,
                                 const float* __restrict__ W_out,
                                 __nv_bfloat16* __restrict__ winh,
                                 __nv_bfloat16* __restrict__ winl,
                                 __nv_bfloat16* __restrict__ wouth,
                                 __nv_bfloat16* __restrict__ woutl)
{
    const int SZ = EE * DIM;
    int idx = blockIdx.x * blockDim.x + threadIdx.x;
    if (idx >= 2 * SZ) return;
    const float* s; __nv_bfloat16 *dh, *dl; int j;
    if (idx < SZ) { s = W_in;  j = idx;      dh = winh;  dl = winl;  }
    else          { s = W_out; j = idx - SZ; dh = wouth; dl = woutl; }
    float v = s[j];
    __nv_bfloat16 h = __float2bfloat16(v);
    dh[j] = h;
    dl[j] = __float2bfloat16(v - __bfloat162float(h));
}

// ======================= HMMA (mma.sync) GEMM ================================
// C[M,N] = A[M,K] * B[N,K]^T + bias (+resid), A/B given as bf16 hi/lo pairs;
// 3 products: Ah*Bh + Ah*Bl + Al*Bh (fp32 accumulate).
// CTA tile 128x128x16, 256 threads, 8 warps (2x4), warp tile 64x32.
// ldmatrix.x4 fragment loads; static shared 48KB exactly.

#define BKT   16
#define PADR  24                       // bf16 per row (16 data + 8 pad) -> 48B rows
#define PLANE (128 * PADR)             // 3072 bf16 per plane
#define STAGE (4 * PLANE)              // Ah, Al, Bh, Bl -> 12288 bf16 (24KB)

__device__ __forceinline__ void mma16816(float* d, const uint32_t* a, const uint32_t* b) {
    asm volatile(
        "mma.sync.aligned.m16n8k16.row.col.f32.bf16.bf16.f32 "
        "{%0,%1,%2,%3}, {%4,%5,%6,%7}, {%8,%9}, {%0,%1,%2,%3};"
        : "+f"(d[0]), "+f"(d[1]), "+f"(d[2]), "+f"(d[3])
        : "r"(a[0]), "r"(a[1]), "r"(a[2]), "r"(a[3]), "r"(b[0]), "r"(b[1]));
}

__device__ __forceinline__ void ldsm4(uint32_t* r, uint32_t addr) {
    asm volatile("ldmatrix.sync.aligned.m8n8.x4.shared.b16 {%0,%1,%2,%3}, [%4];"
                 : "=r"(r[0]), "=r"(r[1]), "=r"(r[2]), "=r"(r[3]) : "r"(addr));
}

#define CP_ASYNC8(s, g) asm volatile("cp.async.ca.shared.global [%0], [%1], 8;" :: "r"(s), "l"(g))
#define CP_COMMIT()     asm volatile("cp.async.commit_group;")
#define CP_WAIT1()      asm volatile("cp.async.wait_group 1;")

template<bool RESID>
__global__ __launch_bounds__(256)
void gemm_mma_kernel(const __nv_bfloat16* __restrict__ Ah,
                     const __nv_bfloat16* __restrict__ Al,
                     const __nv_bfloat16* __restrict__ Bh,
                     const __nv_bfloat16* __restrict__ Bl,
                     const float* __restrict__ bias,
                     const float* __restrict__ resid,
                     float* __restrict__ Cout,
                     int N, int K)
{
    __shared__ __nv_bfloat16 sm[2 * STAGE];     // 49152 bytes, static
    const uint32_t sm32 = smem_u32_(sm);
    const int tid  = threadIdx.x;
    const int wid  = tid >> 5, lane = tid & 31;
    const int g    = lane >> 2;           // 0..7
    const int t2   = (lane & 3) * 2;      // 0,2,4,6
    const int brow = blockIdx.y * 128, bcol = blockIdx.x * 128;
    const int warp_m = (wid >> 2) * 64;   // 0 or 64
    const int warp_n = (wid & 3) * 32;    // 0,32,64,96

    const __nv_bfloat16* gptr[4] = { Ah, Al, Bh, Bl };

    // per-lane ldmatrix byte offsets (within a plane)
    const int arow  = (lane & 7) + 8 * ((lane >> 3) & 1);
    const int akofs = 8 * (lane >> 4);
    const uint32_t a_off = (uint32_t)((warp_m + arow) * PADR + akofs) * 2;
    const int browl = (lane & 7) + 8 * (lane >> 4);
    const int bkofs = 8 * ((lane >> 3) & 1);
    const uint32_t b_off = (uint32_t)((warp_n + browl) * PADR + bkofs) * 2;

    float acc[4][4][4];
    #pragma unroll
    for (int mt = 0; mt < 4; mt++)
        #pragma unroll
        for (int nt = 0; nt < 4; nt++)
            #pragma unroll
            for (int q = 0; q < 4; q++) acc[mt][nt][q] = 0.f;

    auto issue = [&](int st, int kt) {
        uint32_t sb = sm32 + (uint32_t)st * STAGE * 2;
        #pragma unroll
        for (int q = 0; q < 8; q++) {
            int ch = tid + q * 256;
            int p  = ch >> 9;
            int rc = ch & 511;
            int r  = rc >> 2;
            int c  = (rc & 3) * 4;
            int rbase = (p < 2) ? brow : bcol;
            uint32_t sa = sb + (uint32_t)(p * PLANE + r * PADR + c) * 2;
            const __nv_bfloat16* ga = gptr[p] + (size_t)(rbase + r) * K + kt + c;
            CP_ASYNC8(sa, ga);
        }
        CP_COMMIT();
    };

    const int NK = K / BKT;
    issue(0, 0);
    issue(1, BKT);
    CP_WAIT1();
    __syncthreads();

    for (int i = 0; i < NK; i++) {
        const int st = i & 1;
        const uint32_t sbase = sm32 + (uint32_t)st * STAGE * 2;

        uint32_t ah[4][4], al[4][4], bh[2][4], bl[2][4];
        #pragma unroll
        for (int mt = 0; mt < 4; mt++) {
            uint32_t ad = sbase + a_off + (uint32_t)(mt * 16 * PADR) * 2;
            ldsm4(ah[mt], ad);
            ldsm4(al[mt], ad + (uint32_t)PLANE * 2);
        }
        #pragma unroll
        for (int ntp = 0; ntp < 2; ntp++) {
            uint32_t bd = sbase + b_off + (uint32_t)((2 * PLANE) + ntp * 16 * PADR) * 2;
            ldsm4(bh[ntp], bd);
            ldsm4(bl[ntp], bd + (uint32_t)PLANE * 2);
        }

        #pragma unroll
        for (int mt = 0; mt < 4; mt++)
            #pragma unroll
            for (int nt = 0; nt < 4; nt++) {
                const uint32_t* fh = &bh[nt >> 1][(nt & 1) * 2];
                const uint32_t* fl = &bl[nt >> 1][(nt & 1) * 2];
                mma16816(acc[mt][nt], ah[mt], fh);
                mma16816(acc[mt][nt], ah[mt], fl);
                mma16816(acc[mt][nt], al[mt], fh);
            }

        __syncthreads();
        if (i + 2 < NK) issue(st, (i + 2) * BKT);
        else            CP_COMMIT();
        CP_WAIT1();
        __syncthreads();
    }

    #pragma unroll
    for (int mt = 0; mt < 4; mt++) {
        int r0 = brow + warp_m + mt * 16 + g;
        #pragma unroll
        for (int nt = 0; nt < 4; nt++) {
            int c = bcol + warp_n + nt * 8 + t2;
            float2 bv = *(const float2*)&bias[c];
            float2 o0, o1;
            o0.x = acc[mt][nt][0] + bv.x;
            o0.y = acc[mt][nt][1] + bv.y;
            o1.x = acc[mt][nt][2] + bv.x;
            o1.y = acc[mt][nt][3] + bv.y;
            if (RESID) {
                float2 rv0 = *(const float2*)&resid[(size_t)r0 * N + c];
                float2 rv1 = *(const float2*)&resid[(size_t)(r0 + 8) * N + c];
                o0.x += rv0.x; o0.y += rv0.y;
                o1.x += rv1.x; o1.y += rv1.y;
            }
            *(float2*)&Cout[(size_t)r0 * N + c]       = o0;
            *(float2*)&Cout[(size_t)(r0 + 8) * N + c] = o1;
        }
    }
}

// ---------------- K1': per-chunk final states only (conv fused) --------------
__global__ __launch_bounds__(256)
void scan_state_kernel(const float* __restrict__ xp,
                       const float* __restrict__ A,
                       const float* __restrict__ Bp,
                       const float* __restrict__ convw,
                       float* __restrict__ hloc)
{
    int tid = blockIdx.x * blockDim.x + threadIdx.x;   // b*NCH*EE + c*EE + e
    int e  = tid % EE;
    int bc = tid / EE;
    int c  = bc % NCH;
    int b  = bc / NCH;

    float sA[DSTATE], sB[DSTATE], h[DSTATE];
    #pragma unroll
    for (int n = 0; n < DSTATE; n++) {
        sA[n] = sigmoidf_(A [e * DSTATE + n]);
        sB[n] = sigmoidf_(Bp[e * DSTATE + n]);
        h[n] = 0.f;
    }
    float w0 = convw[e * 4 + 0];
    float w1 = convw[e * 4 + 1];
    float w2 = convw[e * 4 + 2];
    float w3 = convw[e * 4 + 3];

    const int t0 = c * CH;
    const float* xb = xp + (size_t)b * LL * EE + e;
    float xm1 = (t0 >= 1) ? xb[(size_t)(t0 - 1) * EE] : 0.f;
    float xm2 = (t0 >= 2) ? xb[(size_t)(t0 - 2) * EE] : 0.f;
    float xm3 = (t0 >= 3) ? xb[(size_t)(t0 - 3) * EE] : 0.f;

    const float* xq = xb + (size_t)t0 * EE;

    #pragma unroll
    for (int tb = 0; tb < CH; tb += 8) {
        float xv[8];
        #pragma unroll
        for (int j = 0; j < 8; j++)
            xv[j] = xq[(size_t)(tb + j) * EE];

        #pragma unroll
        for (int j = 0; j < 8; j++) {
            float xcv = xv[j] * w3 + xm1 * w2 + xm2 * w1 + xm3 * w0;
            xm3 = xm2; xm2 = xm1; xm1 = xv[j];
            #pragma unroll
            for (int n = 0; n < DSTATE; n++)
                h[n] = fmaf(sA[n], h[n], sB[n] * xcv);
        }
    }

    float* hp = hloc + (((size_t)b * NCH + c) * DSTATE) * EE + e;
    #pragma unroll
    for (int n = 0; n < DSTATE; n++)
        hp[(size_t)n * EE] = h[n];
}

// ---------------- K2: combine chunk states sequentially ----------------------
__global__ void chunk_combine_kernel(const float* __restrict__ hloc,
                                     const float* __restrict__ A,
                                     float* __restrict__ hin)
{
    int tid = blockIdx.x * blockDim.x + threadIdx.x;   // b*DSTATE*EE + n*EE + e
    int e  = tid % EE;
    int bn = tid / EE;
    int n  = bn % DSTATE;
    int b  = bn / DSTATE;

    float sA = sigmoidf_(A[e * DSTATE + n]);
    float pw = sA;
    #pragma unroll
    for (int i = 0; i < 5; i++) pw *= pw;              // sA^32 (CH=32)

    size_t base = ((size_t)b * NCH * DSTATE + n) * EE + e;
    const size_t cstride = (size_t)DSTATE * EE;

    float h = 0.f;
    #pragma unroll
    for (int c = 0; c < NCH; c++) {
        hin[base + c * cstride] = h;
        h = fmaf(pw, h, hloc[base + c * cstride]);
    }
}

// ---------------- K3': full scan from hin, bf16 split output -----------------
__global__ __launch_bounds__(256)
void scan_out_kernel(const float* __restrict__ xp,
                     const float* __restrict__ hin,
                     const float* __restrict__ A,
                     const float* __restrict__ Bp,
                     const float* __restrict__ C,
                     const float* __restrict__ convw,
                     __nv_bfloat16* __restrict__ yh,
                     __nv_bfloat16* __restrict__ yl)
{
    int tid = blockIdx.x * blockDim.x + threadIdx.x;   // b*NCH*EE + c*EE + e
    int e  = tid % EE;
    int bc = tid / EE;
    int c  = bc % NCH;
    int b  = bc / NCH;

    float sA[DSTATE], sB[DSTATE], sC[DSTATE], h[DSTATE];
    const float* hp = hin + (((size_t)b * NCH + c) * DSTATE) * EE + e;
    #pragma unroll
    for (int n = 0; n < DSTATE; n++) {
        sA[n] = sigmoidf_(A [e * DSTATE + n]);
        sB[n] = sigmoidf_(Bp[e * DSTATE + n]);
        sC[n] = sigmoidf_(C [e * DSTATE + n]);
        h[n] = (c > 0) ? hp[(size_t)n * EE] : 0.f;
    }
    float w0 = convw[e * 4 + 0];
    float w1 = convw[e * 4 + 1];
    float w2 = convw[e * 4 + 2];
    float w3 = convw[e * 4 + 3];

    const int t0 = c * CH;
    const float* xb = xp + (size_t)b * LL * EE + e;
    float xm1 = (t0 >= 1) ? xb[(size_t)(t0 - 1) * EE] : 0.f;
    float xm2 = (t0 >= 2) ? xb[(size_t)(t0 - 2) * EE] : 0.f;
    float xm3 = (t0 >= 3) ? xb[(size_t)(t0 - 3) * EE] : 0.f;

    const float* xq = xb + (size_t)t0 * EE;
    size_t obase = ((size_t)b * LL + t0) * EE + e;
    __nv_bfloat16* yhb = yh + obase;
    __nv_bfloat16* ylb = yl + obase;

    #pragma unroll
    for (int tb = 0; tb < CH; tb += 8) {
        float xv[8];
        #pragma unroll
        for (int j = 0; j < 8; j++)
            xv[j] = xq[(size_t)(tb + j) * EE];

        #pragma unroll
        for (int j = 0; j < 8; j++) {
            float xcv = xv[j] * w3 + xm1 * w2 + xm2 * w1 + xm3 * w0;
            xm3 = xm2; xm2 = xm1; xm1 = xv[j];

            float a0 = 0.f, a1 = 0.f, a2 = 0.f, a3 = 0.f;
            #pragma unroll
            for (int n = 0; n < DSTATE; n += 4) {
                h[n + 0] = fmaf(sA[n + 0], h[n + 0], sB[n + 0] * xcv);
                h[n + 1] = fmaf(sA[n + 1], h[n + 1], sB[n + 1] * xcv);
                h[n + 2] = fmaf(sA[n + 2], h[n + 2], sB[n + 2] * xcv);
                h[n + 3] = fmaf(sA[n + 3], h[n + 3], sB[n + 3] * xcv);
                a0 = fmaf(sC[n + 0], h[n + 0], a0);
                a1 = fmaf(sC[n + 1], h[n + 1], a1);
                a2 = fmaf(sC[n + 2], h[n + 2], a2);
                a3 = fmaf(sC[n + 3], h[n + 3], a3);
            }
            float v = (a0 + a1) + (a2 + a3);
            __nv_bfloat16 hv = __float2bfloat16(v);
            yhb[(size_t)(tb + j) * EE] = hv;
            ylb[(size_t)(tb + j) * EE] = __float2bfloat16(v - __bfloat162float(hv));
        }
    }
}

// ---------------- launch -----------------------------------------------------
extern "C" void kernel_launch(void* const* d_in, const int* in_sizes, int n_in,
                              void* d_out, int out_size)
{
    const float* x      = (const float*)d_in[0];
    const float* gamma  = (const float*)d_in[1];
    const float* W_in   = (const float*)d_in[2];
    const float* b_in   = (const float*)d_in[3];
    const float* conv_w = (const float*)d_in[4];
    const float* A      = (const float*)d_in[5];
    const float* Bp     = (const float*)d_in[6];
    const float* C      = (const float*)d_in[7];
    const float* W_out  = (const float*)d_in[8];
    const float* b_out  = (const float*)d_in[9];
    float* out = (float*)d_out;

    float *xp, *hloc, *hin;
    __nv_bfloat16 *xnh, *xnl, *winh, *winl, *wouth, *woutl, *yh, *yl;
    cudaGetSymbolAddress((void**)&xp,    g_xp);
    cudaGetSymbolAddress((void**)&hloc,  g_hloc);
    cudaGetSymbolAddress((void**)&hin,   g_hin);
    cudaGetSymbolAddress((void**)&xnh,   g_xnh);
    cudaGetSymbolAddress((void**)&xnl,   g_xnl);
    cudaGetSymbolAddress((void**)&winh,  g_winh);
    cudaGetSymbolAddress((void**)&winl,  g_winl);
    cudaGetSymbolAddress((void**)&wouth, g_wouth);
    cudaGetSymbolAddress((void**)&woutl, g_woutl);
    cudaGetSymbolAddress((void**)&yh,    g_yh);
    cudaGetSymbolAddress((void**)&yl,    g_yl);

    // 1. rmsnorm -> bf16 hi/lo
    rmsnorm_kernel<<<BL, 256>>>(x, gamma, xnh, xnl);

    // 1b. convert weights -> bf16 hi/lo
    convert_w_kernel<<<(2 * EE * DIM + 255) / 256, 256>>>(W_in, W_out,
                                                          winh, winl, wouth, woutl);

    // 2. in-proj (HMMA): xp = xn @ W_in^T + b_in
    {
        dim3 grid(EE / 128, BL / 128);
        gemm_mma_kernel<false><<<grid, 256>>>(xnh, xnl, winh, winl,
                                              b_in, nullptr, xp, EE, DIM);
    }

    // 3. chunked scan (conv fused); no fp32 y intermediate
    {
        int threads = BB * NCH * EE;                   // 196608
        scan_state_kernel<<<threads / 256, 256>>>(xp, A, Bp, conv_w, hloc);
    }
    {
        int threads = BB * DSTATE * EE;                // 49152
        chunk_combine_kernel<<<threads / 256, 256>>>(hloc, A, hin);
    }
    {
        int threads = BB * NCH * EE;
        scan_out_kernel<<<threads / 256, 256>>>(xp, hin, A, Bp, C, conv_w, yh, yl);
    }

    // 4. out-proj + residual (HMMA): out = y @ W_out^T + b_out + x
    {
        dim3 grid(DIM / 128, BL / 128);
        gemm_mma_kernel<true><<<grid, 256>>>(yh, yl, wouth, woutl,
                                             b_out, x, out, DIM, EE);
    }
}

// round 11
// speedup vs baseline: 2.6545x; 1.0656x over previous
#include <cuda_runtime.h>
#include <cuda_bf16.h>
#include <math.h>
#include <stdint.h>

#define DIM    768
#define DSTATE 16
#define DCONV  4
#define EE     1536          // expand dim
#define BB     2
#define LL     2048
#define BL     (BB*LL)       // 4096
#define EPS    1e-6f

#define CH     32            // chunk length
#define NCH    (LL/CH)       // 64 chunks

// ---------------- scratch (static device arrays; no allocations) -------------
__device__ float          g_xp  [BL * EE];              // after in-proj (fp32)
__device__ float          g_hloc[BB * NCH * DSTATE * EE];   // per-chunk final g
__device__ float          g_hin [BB * NCH * DSTATE * EE];   // per-chunk incoming g
__device__ __nv_bfloat16  g_xnh [BL * DIM];             // rmsnorm out hi
__device__ __nv_bfloat16  g_xnl [BL * DIM];             // rmsnorm out lo
__device__ __nv_bfloat16  g_winh[EE * DIM];
__device__ __nv_bfloat16  g_winl[EE * DIM];
__device__ __nv_bfloat16  g_wouth[DIM * EE];
__device__ __nv_bfloat16  g_woutl[DIM * EE];
__device__ __nv_bfloat16  g_yh  [BL * EE];              // final scan out hi
__device__ __nv_bfloat16  g_yl  [BL * EE];              // final scan out lo

__device__ __forceinline__ float sigmoidf_(float v) {
    return 1.0f / (1.0f + expf(-v));
}

__device__ __forceinline__ uint32_t smem_u32_(const void* p) {
    uint32_t a;
    asm("{ .reg .u64 t; cvta.to.shared.u64 t, %1; cvt.u32.u64 %0, t; }"
        : "=r"(a) : "l"(p));
    return a;
}

// ---------------- rmsnorm (writes bf16 hi/lo split) --------------------------
__global__ void rmsnorm_kernel(const float* __restrict__ x,
                               const float* __restrict__ gamma,
                               __nv_bfloat16* __restrict__ xnh,
                               __nv_bfloat16* __restrict__ xnl)
{
    const int row = blockIdx.x;
    const float* xr = x + (size_t)row * DIM;

    float v0 = xr[threadIdx.x];
    float v1 = xr[threadIdx.x + 256];
    float v2 = xr[threadIdx.x + 512];
    float ss = v0 * v0 + v1 * v1 + v2 * v2;

    #pragma unroll
    for (int o = 16; o > 0; o >>= 1)
        ss += __shfl_xor_sync(0xffffffffu, ss, o);

    __shared__ float warp_s[8];
    int wid = threadIdx.x >> 5, lane = threadIdx.x & 31;
    if (lane == 0) warp_s[wid] = ss;
    __syncthreads();
    if (wid == 0) {
        float t = (lane < 8) ? warp_s[lane] : 0.f;
        #pragma unroll
        for (int o = 4; o > 0; o >>= 1)
            t += __shfl_xor_sync(0xffffffffu, t, o);
        if (lane == 0) warp_s[0] = t;
    }
    __syncthreads();
    float rms = sqrtf(warp_s[0] * (1.0f / DIM));
    float inv = 1.0f / (rms + EPS);

    #pragma unroll
    for (int k = 0; k < 3; k++) {
        int i = threadIdx.x + k * 256;
        float v = (k == 0) ? v0 : (k == 1) ? v1 : v2;
        float o = gamma[i] * v * inv;
        __nv_bfloat16 h = __float2bfloat16(o);
        xnh[(size_t)row * DIM + i] = h;
        xnl[(size_t)row * DIM + i] = __float2bfloat16(o - __bfloat162float(h));
    }
}

// ---------------- weight conversion fp32 -> bf16 hi/lo -----------------------
__global__ void convert_w_kernel(const float* __restrict__ W_in,
                                 const float* __restrict__ W_out,
                                 __nv_bfloat16* __restrict__ winh,
                                 __nv_bfloat16* __restrict__ winl,
                                 __nv_bfloat16* __restrict__ wouth,
                                 __nv_bfloat16* __restrict__ woutl)
{
    const int SZ = EE * DIM;
    int idx = blockIdx.x * blockDim.x + threadIdx.x;
    if (idx >= 2 * SZ) return;
    const float* s; __nv_bfloat16 *dh, *dl; int j;
    if (idx < SZ) { s = W_in;  j = idx;      dh = winh;  dl = winl;  }
    else          { s = W_out; j = idx - SZ; dh = wouth; dl = woutl; }
    float v = s[j];
    __nv_bfloat16 h = __float2bfloat16(v);
    dh[j] = h;
    dl[j] = __float2bfloat16(v - __bfloat162float(h));
}

// ======================= HMMA (mma.sync) GEMM ================================
// C[M,N] = A[M,K] * B[N,K]^T + bias (+resid), A/B given as bf16 hi/lo pairs;
// 3 products: Ah*Bh + Ah*Bl + Al*Bh (fp32 accumulate).
// CTA tile 128x128x16, 256 threads, 8 warps (2x4), warp tile 64x32.
// ldmatrix.x4 fragment loads; static shared 48KB exactly.

#define BKT   16
#define PADR  24                       // bf16 per row (16 data + 8 pad) -> 48B rows
#define PLANE (128 * PADR)             // 3072 bf16 per plane
#define STAGE (4 * PLANE)              // Ah, Al, Bh, Bl -> 12288 bf16 (24KB)

__device__ __forceinline__ void mma16816(float* d, const uint32_t* a, const uint32_t* b) {
    asm volatile(
        "mma.sync.aligned.m16n8k16.row.col.f32.bf16.bf16.f32 "
        "{%0,%1,%2,%3}, {%4,%5,%6,%7}, {%8,%9}, {%0,%1,%2,%3};"
        : "+f"(d[0]), "+f"(d[1]), "+f"(d[2]), "+f"(d[3])
        : "r"(a[0]), "r"(a[1]), "r"(a[2]), "r"(a[3]), "r"(b[0]), "r"(b[1]));
}

__device__ __forceinline__ void ldsm4(uint32_t* r, uint32_t addr) {
    asm volatile("ldmatrix.sync.aligned.m8n8.x4.shared.b16 {%0,%1,%2,%3}, [%4];"
                 : "=r"(r[0]), "=r"(r[1]), "=r"(r[2]), "=r"(r[3]) : "r"(addr));
}

#define CP_ASYNC8(s, g) asm volatile("cp.async.ca.shared.global [%0], [%1], 8;" :: "r"(s), "l"(g))
#define CP_COMMIT()     asm volatile("cp.async.commit_group;")
#define CP_WAIT1()      asm volatile("cp.async.wait_group 1;")

template<bool RESID>
__global__ __launch_bounds__(256)
void gemm_mma_kernel(const __nv_bfloat16* __restrict__ Ah,
                     const __nv_bfloat16* __restrict__ Al,
                     const __nv_bfloat16* __restrict__ Bh,
                     const __nv_bfloat16* __restrict__ Bl,
                     const float* __restrict__ bias,
                     const float* __restrict__ resid,
                     float* __restrict__ Cout,
                     int N, int K)
{
    __shared__ __nv_bfloat16 sm[2 * STAGE];     // 49152 bytes, static
    const uint32_t sm32 = smem_u32_(sm);
    const int tid  = threadIdx.x;
    const int wid  = tid >> 5, lane = tid & 31;
    const int g    = lane >> 2;
    const int t2   = (lane & 3) * 2;
    const int brow = blockIdx.y * 128, bcol = blockIdx.x * 128;
    const int warp_m = (wid >> 2) * 64;
    const int warp_n = (wid & 3) * 32;

    const __nv_bfloat16* gptr[4] = { Ah, Al, Bh, Bl };

    const int arow  = (lane & 7) + 8 * ((lane >> 3) & 1);
    const int akofs = 8 * (lane >> 4);
    const uint32_t a_off = (uint32_t)((warp_m + arow) * PADR + akofs) * 2;
    const int browl = (lane & 7) + 8 * (lane >> 4);
    const int bkofs = 8 * ((lane >> 3) & 1);
    const uint32_t b_off = (uint32_t)((warp_n + browl) * PADR + bkofs) * 2;

    float acc[4][4][4];
    #pragma unroll
    for (int mt = 0; mt < 4; mt++)
        #pragma unroll
        for (int nt = 0; nt < 4; nt++)
            #pragma unroll
            for (int q = 0; q < 4; q++) acc[mt][nt][q] = 0.f;

    auto issue = [&](int st, int kt) {
        uint32_t sb = sm32 + (uint32_t)st * STAGE * 2;
        #pragma unroll
        for (int q = 0; q < 8; q++) {
            int ch = tid + q * 256;
            int p  = ch >> 9;
            int rc = ch & 511;
            int r  = rc >> 2;
            int c  = (rc & 3) * 4;
            int rbase = (p < 2) ? brow : bcol;
            uint32_t sa = sb + (uint32_t)(p * PLANE + r * PADR + c) * 2;
            const __nv_bfloat16* ga = gptr[p] + (size_t)(rbase + r) * K + kt + c;
            CP_ASYNC8(sa, ga);
        }
        CP_COMMIT();
    };

    const int NK = K / BKT;
    issue(0, 0);
    issue(1, BKT);
    CP_WAIT1();
    __syncthreads();

    for (int i = 0; i < NK; i++) {
        const int st = i & 1;
        const uint32_t sbase = sm32 + (uint32_t)st * STAGE * 2;

        uint32_t ah[4][4], al[4][4], bh[2][4], bl[2][4];
        #pragma unroll
        for (int mt = 0; mt < 4; mt++) {
            uint32_t ad = sbase + a_off + (uint32_t)(mt * 16 * PADR) * 2;
            ldsm4(ah[mt], ad);
            ldsm4(al[mt], ad + (uint32_t)PLANE * 2);
        }
        #pragma unroll
        for (int ntp = 0; ntp < 2; ntp++) {
            uint32_t bd = sbase + b_off + (uint32_t)((2 * PLANE) + ntp * 16 * PADR) * 2;
            ldsm4(bh[ntp], bd);
            ldsm4(bl[ntp], bd + (uint32_t)PLANE * 2);
        }

        #pragma unroll
        for (int mt = 0; mt < 4; mt++)
            #pragma unroll
            for (int nt = 0; nt < 4; nt++) {
                const uint32_t* fh = &bh[nt >> 1][(nt & 1) * 2];
                const uint32_t* fl = &bl[nt >> 1][(nt & 1) * 2];
                mma16816(acc[mt][nt], ah[mt], fh);
                mma16816(acc[mt][nt], ah[mt], fl);
                mma16816(acc[mt][nt], al[mt], fh);
            }

        __syncthreads();
        if (i + 2 < NK) issue(st, (i + 2) * BKT);
        else            CP_COMMIT();
        CP_WAIT1();
        __syncthreads();
    }

    #pragma unroll
    for (int mt = 0; mt < 4; mt++) {
        int r0 = brow + warp_m + mt * 16 + g;
        #pragma unroll
        for (int nt = 0; nt < 4; nt++) {
            int c = bcol + warp_n + nt * 8 + t2;
            float2 bv = *(const float2*)&bias[c];
            float2 o0, o1;
            o0.x = acc[mt][nt][0] + bv.x;
            o0.y = acc[mt][nt][1] + bv.y;
            o1.x = acc[mt][nt][2] + bv.x;
            o1.y = acc[mt][nt][3] + bv.y;
            if (RESID) {
                float2 rv0 = *(const float2*)&resid[(size_t)r0 * N + c];
                float2 rv1 = *(const float2*)&resid[(size_t)(r0 + 8) * N + c];
                o0.x += rv0.x; o0.y += rv0.y;
                o1.x += rv1.x; o1.y += rv1.y;
            }
            *(float2*)&Cout[(size_t)r0 * N + c]       = o0;
            *(float2*)&Cout[(size_t)(r0 + 8) * N + c] = o1;
        }
    }
}

// ---------------- K1: per-chunk final g-states (conv fused) ------------------
// g-recurrence: g = sA*g + xcv  (h = sB*g; sB divided out -> 16 FMA/t)
__global__ __launch_bounds__(256)
void scan_state_kernel(const float* __restrict__ xp,
                       const float* __restrict__ A,
                       const float* __restrict__ convw,
                       float* __restrict__ hloc)
{
    int tid = blockIdx.x * blockDim.x + threadIdx.x;   // b*NCH*EE + c*EE + e
    int e  = tid % EE;
    int bc = tid / EE;
    int c  = bc % NCH;
    int b  = bc / NCH;

    float sA[DSTATE], g[DSTATE];
    #pragma unroll
    for (int n = 0; n < DSTATE; n++) {
        sA[n] = sigmoidf_(A[e * DSTATE + n]);
        g[n] = 0.f;
    }
    float w0 = convw[e * 4 + 0];
    float w1 = convw[e * 4 + 1];
    float w2 = convw[e * 4 + 2];
    float w3 = convw[e * 4 + 3];

    const int t0 = c * CH;
    const float* xb = xp + (size_t)b * LL * EE + e;
    float xm1 = (t0 >= 1) ? xb[(size_t)(t0 - 1) * EE] : 0.f;
    float xm2 = (t0 >= 2) ? xb[(size_t)(t0 - 2) * EE] : 0.f;
    float xm3 = (t0 >= 3) ? xb[(size_t)(t0 - 3) * EE] : 0.f;

    const float* xq = xb + (size_t)t0 * EE;

    #pragma unroll
    for (int tb = 0; tb < CH; tb += 8) {
        float xv[8];
        #pragma unroll
        for (int j = 0; j < 8; j++)
            xv[j] = xq[(size_t)(tb + j) * EE];

        #pragma unroll
        for (int j = 0; j < 8; j++) {
            float xcv = xv[j] * w3 + xm1 * w2 + xm2 * w1 + xm3 * w0;
            xm3 = xm2; xm2 = xm1; xm1 = xv[j];
            #pragma unroll
            for (int n = 0; n < DSTATE; n++)
                g[n] = fmaf(sA[n], g[n], xcv);
        }
    }

    float* hp = hloc + (((size_t)b * NCH + c) * DSTATE) * EE + e;
    #pragma unroll
    for (int n = 0; n < DSTATE; n++)
        hp[(size_t)n * EE] = g[n];
}

// ---------------- K2: combine chunk g-states sequentially --------------------
__global__ void chunk_combine_kernel(const float* __restrict__ hloc,
                                     const float* __restrict__ A,
                                     float* __restrict__ hin)
{
    int tid = blockIdx.x * blockDim.x + threadIdx.x;   // b*DSTATE*EE + n*EE + e
    int e  = tid % EE;
    int bn = tid / EE;
    int n  = bn % DSTATE;
    int b  = bn / DSTATE;

    float sA = sigmoidf_(A[e * DSTATE + n]);
    float pw = sA;
    #pragma unroll
    for (int i = 0; i < 5; i++) pw *= pw;              // sA^32 (CH=32)

    size_t base = ((size_t)b * NCH * DSTATE + n) * EE + e;
    const size_t cstride = (size_t)DSTATE * EE;

    float h = 0.f;
    #pragma unroll
    for (int c = 0; c < NCH; c++) {
        hin[base + c * cstride] = h;
        h = fmaf(pw, h, hloc[base + c * cstride]);
    }
}

// ---------------- K3: full g-scan from hin, y = sum sCB*g, bf16 split --------
__global__ __launch_bounds__(256)
void scan_out_kernel(const float* __restrict__ xp,
                     const float* __restrict__ hin,
                     const float* __restrict__ A,
                     const float* __restrict__ Bp,
                     const float* __restrict__ C,
                     const float* __restrict__ convw,
                     __nv_bfloat16* __restrict__ yh,
                     __nv_bfloat16* __restrict__ yl)
{
    int tid = blockIdx.x * blockDim.x + threadIdx.x;   // b*NCH*EE + c*EE + e
    int e  = tid % EE;
    int bc = tid / EE;
    int c  = bc % NCH;
    int b  = bc / NCH;

    float sA[DSTATE], sCB[DSTATE], g[DSTATE];
    const float* hp = hin + (((size_t)b * NCH + c) * DSTATE) * EE + e;
    #pragma unroll
    for (int n = 0; n < DSTATE; n++) {
        sA[n]  = sigmoidf_(A[e * DSTATE + n]);
        sCB[n] = sigmoidf_(C[e * DSTATE + n]) * sigmoidf_(Bp[e * DSTATE + n]);
        g[n]   = (c > 0) ? hp[(size_t)n * EE] : 0.f;
    }
    float w0 = convw[e * 4 + 0];
    float w1 = convw[e * 4 + 1];
    float w2 = convw[e * 4 + 2];
    float w3 = convw[e * 4 + 3];

    const int t0 = c * CH;
    const float* xb = xp + (size_t)b * LL * EE + e;
    float xm1 = (t0 >= 1) ? xb[(size_t)(t0 - 1) * EE] : 0.f;
    float xm2 = (t0 >= 2) ? xb[(size_t)(t0 - 2) * EE] : 0.f;
    float xm3 = (t0 >= 3) ? xb[(size_t)(t0 - 3) * EE] : 0.f;

    const float* xq = xb + (size_t)t0 * EE;
    size_t obase = ((size_t)b * LL + t0) * EE + e;
    __nv_bfloat16* yhb = yh + obase;
    __nv_bfloat16* ylb = yl + obase;

    #pragma unroll
    for (int tb = 0; tb < CH; tb += 8) {
        float xv[8];
        #pragma unroll
        for (int j = 0; j < 8; j++)
            xv[j] = xq[(size_t)(tb + j) * EE];

        #pragma unroll
        for (int j = 0; j < 8; j++) {
            float xcv = xv[j] * w3 + xm1 * w2 + xm2 * w1 + xm3 * w0;
            xm3 = xm2; xm2 = xm1; xm1 = xv[j];

            float a0 = 0.f, a1 = 0.f, a2 = 0.f, a3 = 0.f;
            #pragma unroll
            for (int n = 0; n < DSTATE; n += 4) {
                g[n + 0] = fmaf(sA[n + 0], g[n + 0], xcv);
                g[n + 1] = fmaf(sA[n + 1], g[n + 1], xcv);
                g[n + 2] = fmaf(sA[n + 2], g[n + 2], xcv);
                g[n + 3] = fmaf(sA[n + 3], g[n + 3], xcv);
                a0 = fmaf(sCB[n + 0], g[n + 0], a0);
                a1 = fmaf(sCB[n + 1], g[n + 1], a1);
                a2 = fmaf(sCB[n + 2], g[n + 2], a2);
                a3 = fmaf(sCB[n + 3], g[n + 3], a3);
            }
            float v = (a0 + a1) + (a2 + a3);
            __nv_bfloat16 hv = __float2bfloat16(v);
            yhb[(size_t)(tb + j) * EE] = hv;
            ylb[(size_t)(tb + j) * EE] = __float2bfloat16(v - __bfloat162float(hv));
        }
    }
}

// ---------------- launch -----------------------------------------------------
extern "C" void kernel_launch(void* const* d_in, const int* in_sizes, int n_in,
                              void* d_out, int out_size)
{
    const float* x      = (const float*)d_in[0];
    const float* gamma  = (const float*)d_in[1];
    const float* W_in   = (const float*)d_in[2];
    const float* b_in   = (const float*)d_in[3];
    const float* conv_w = (const float*)d_in[4];
    const float* A      = (const float*)d_in[5];
    const float* Bp     = (const float*)d_in[6];
    const float* C      = (const float*)d_in[7];
    const float* W_out  = (const float*)d_in[8];
    const float* b_out  = (const float*)d_in[9];
    float* out = (float*)d_out;

    float *xp, *hloc, *hin;
    __nv_bfloat16 *xnh, *xnl, *winh, *winl, *wouth, *woutl, *yh, *yl;
    cudaGetSymbolAddress((void**)&xp,    g_xp);
    cudaGetSymbolAddress((void**)&hloc,  g_hloc);
    cudaGetSymbolAddress((void**)&hin,   g_hin);
    cudaGetSymbolAddress((void**)&xnh,   g_xnh);
    cudaGetSymbolAddress((void**)&xnl,   g_xnl);
    cudaGetSymbolAddress((void**)&winh,  g_winh);
    cudaGetSymbolAddress((void**)&winl,  g_winl);
    cudaGetSymbolAddress((void**)&wouth, g_wouth);
    cudaGetSymbolAddress((void**)&woutl, g_woutl);
    cudaGetSymbolAddress((void**)&yh,    g_yh);
    cudaGetSymbolAddress((void**)&yl,    g_yl);

    // 1. rmsnorm -> bf16 hi/lo
    rmsnorm_kernel<<<BL, 256>>>(x, gamma, xnh, xnl);

    // 1b. convert weights -> bf16 hi/lo
    convert_w_kernel<<<(2 * EE * DIM + 255) / 256, 256>>>(W_in, W_out,
                                                          winh, winl, wouth, woutl);

    // 2. in-proj (HMMA): xp = xn @ W_in^T + b_in
    {
        dim3 grid(EE / 128, BL / 128);
        gemm_mma_kernel<false><<<grid, 256>>>(xnh, xnl, winh, winl,
                                              b_in, nullptr, xp, EE, DIM);
    }

    // 3. chunked g-scan (conv fused)
    {
        int threads = BB * NCH * EE;                   // 196608
        scan_state_kernel<<<threads / 256, 256>>>(xp, A, conv_w, hloc);
    }
    {
        int threads = BB * DSTATE * EE;                // 49152
        chunk_combine_kernel<<<threads / 256, 256>>>(hloc, A, hin);
    }
    {
        int threads = BB * NCH * EE;
        scan_out_kernel<<<threads / 256, 256>>>(xp, hin, A, Bp, C, conv_w, yh, yl);
    }

    // 4. out-proj + residual (HMMA): out = y @ W_out^T + b_out + x
    {
        dim3 grid(DIM / 128, BL / 128);
        gemm_mma_kernel<true><<<grid, 256>>>(yh, yl, wouth, woutl,
                                             b_out, x, out, DIM, EE);
    }
}

// round 12
// speedup vs baseline: 2.8468x; 1.0724x over previous
#include <cuda_runtime.h>
#include <cuda_bf16.h>
#include <math.h>
#include <stdint.h>

#define DIM    768
#define DSTATE 16
#define DCONV  4
#define EE     1536          // expand dim
#define BB     2
#define LL     2048
#define BL     (BB*LL)       // 4096
#define EPS    1e-6f

#define CH     32            // chunk length
#define NCH    (LL/CH)       // 64 chunks

// ---------------- scratch (static device arrays; no allocations) -------------
__device__ float          g_xp  [BL * EE];              // after in-proj (fp32)
__device__ float          g_hloc[BB * NCH * DSTATE * EE];   // per-chunk final g
__device__ float          g_hin [BB * NCH * DSTATE * EE];   // per-chunk incoming g
__device__ __nv_bfloat16  g_xnh [BL * DIM];             // rmsnorm out hi
__device__ __nv_bfloat16  g_xnl [BL * DIM];             // rmsnorm out lo
__device__ __nv_bfloat16  g_winh[EE * DIM];
__device__ __nv_bfloat16  g_winl[EE * DIM];
__device__ __nv_bfloat16  g_wouth[DIM * EE];
__device__ __nv_bfloat16  g_woutl[DIM * EE];
__device__ __nv_bfloat16  g_yh  [BL * EE];              // final scan out hi
__device__ __nv_bfloat16  g_yl  [BL * EE];              // final scan out lo

__device__ __forceinline__ float sigmoidf_(float v) {
    return 1.0f / (1.0f + expf(-v));
}

__device__ __forceinline__ uint32_t smem_u32_(const void* p) {
    uint32_t a;
    asm("{ .reg .u64 t; cvta.to.shared.u64 t, %1; cvt.u32.u64 %0, t; }"
        : "=r"(a) : "l"(p));
    return a;
}

// ---------------- rmsnorm (writes bf16 hi/lo split) --------------------------
__global__ void rmsnorm_kernel(const float* __restrict__ x,
                               const float* __restrict__ gamma,
                               __nv_bfloat16* __restrict__ xnh,
                               __nv_bfloat16* __restrict__ xnl)
{
    const int row = blockIdx.x;
    const float* xr = x + (size_t)row * DIM;

    float v0 = xr[threadIdx.x];
    float v1 = xr[threadIdx.x + 256];
    float v2 = xr[threadIdx.x + 512];
    float ss = v0 * v0 + v1 * v1 + v2 * v2;

    #pragma unroll
    for (int o = 16; o > 0; o >>= 1)
        ss += __shfl_xor_sync(0xffffffffu, ss, o);

    __shared__ float warp_s[8];
    int wid = threadIdx.x >> 5, lane = threadIdx.x & 31;
    if (lane == 0) warp_s[wid] = ss;
    __syncthreads();
    if (wid == 0) {
        float t = (lane < 8) ? warp_s[lane] : 0.f;
        #pragma unroll
        for (int o = 4; o > 0; o >>= 1)
            t += __shfl_xor_sync(0xffffffffu, t, o);
        if (lane == 0) warp_s[0] = t;
    }
    __syncthreads();
    float rms = sqrtf(warp_s[0] * (1.0f / DIM));
    float inv = 1.0f / (rms + EPS);

    #pragma unroll
    for (int k = 0; k < 3; k++) {
        int i = threadIdx.x + k * 256;
        float v = (k == 0) ? v0 : (k == 1) ? v1 : v2;
        float o = gamma[i] * v * inv;
        __nv_bfloat16 h = __float2bfloat16(o);
        xnh[(size_t)row * DIM + i] = h;
        xnl[(size_t)row * DIM + i] = __float2bfloat16(o - __bfloat162float(h));
    }
}

// ---------------- weight conversion fp32 -> bf16 hi/lo -----------------------
__global__ void convert_w_kernel(const float* __restrict__ W_in,
                                 const float* __restrict__ W_out,
                                 __nv_bfloat16* __restrict__ winh,
                                 __nv_bfloat16* __restrict__ winl,
                                 __nv_bfloat16* __restrict__ wouth,
                                 __nv_bfloat16* __restrict__ woutl)
{
    const int SZ = EE * DIM;
    int idx = blockIdx.x * blockDim.x + threadIdx.x;
    if (idx >= 2 * SZ) return;
    const float* s; __nv_bfloat16 *dh, *dl; int j;
    if (idx < SZ) { s = W_in;  j = idx;      dh = winh;  dl = winl;  }
    else          { s = W_out; j = idx - SZ; dh = wouth; dl = woutl; }
    float v = s[j];
    __nv_bfloat16 h = __float2bfloat16(v);
    dh[j] = h;
    dl[j] = __float2bfloat16(v - __bfloat162float(h));
}

// ======================= HMMA (mma.sync) GEMM ================================
// C[M,N] = A[M,K] * B[N,K]^T + bias (+resid), A/B given as bf16 hi/lo pairs;
// 3 products: Ah*Bh + Ah*Bl + Al*Bh (fp32 accumulate).
// CTA tile 128x128x32, 256 threads, 8 warps (2x4), warp tile 64x32.
// 16B cp.async staging, 2-stage double buffer, 80KB dynamic smem.

#define BKT   32
#define PADR  40                       // bf16 per row (32 data + 8 pad) -> 80B rows
#define PLANE (128 * PADR)             // 5120 bf16 per plane
#define STAGE (4 * PLANE)              // Ah, Al, Bh, Bl -> 20480 bf16 (40KB)
#define SMEM_GEMM (2 * STAGE * 2)      // 81920 bytes

__device__ __forceinline__ void mma16816(float* d, const uint32_t* a, const uint32_t* b) {
    asm volatile(
        "mma.sync.aligned.m16n8k16.row.col.f32.bf16.bf16.f32 "
        "{%0,%1,%2,%3}, {%4,%5,%6,%7}, {%8,%9}, {%0,%1,%2,%3};"
        : "+f"(d[0]), "+f"(d[1]), "+f"(d[2]), "+f"(d[3])
        : "r"(a[0]), "r"(a[1]), "r"(a[2]), "r"(a[3]), "r"(b[0]), "r"(b[1]));
}

__device__ __forceinline__ void ldsm4(uint32_t* r, uint32_t addr) {
    asm volatile("ldmatrix.sync.aligned.m8n8.x4.shared.b16 {%0,%1,%2,%3}, [%4];"
                 : "=r"(r[0]), "=r"(r[1]), "=r"(r[2]), "=r"(r[3]) : "r"(addr));
}

#define CP_ASYNC16(s, g) asm volatile("cp.async.cg.shared.global [%0], [%1], 16;" :: "r"(s), "l"(g))
#define CP_COMMIT()      asm volatile("cp.async.commit_group;")
#define CP_WAIT1()       asm volatile("cp.async.wait_group 1;")

template<bool RESID>
__global__ __launch_bounds__(256, 2)
void gemm_mma_kernel(const __nv_bfloat16* __restrict__ Ah,
                     const __nv_bfloat16* __restrict__ Al,
                     const __nv_bfloat16* __restrict__ Bh,
                     const __nv_bfloat16* __restrict__ Bl,
                     const float* __restrict__ bias,
                     const float* __restrict__ resid,
                     float* __restrict__ Cout,
                     int N, int K)
{
    extern __shared__ __nv_bfloat16 sm[];       // 81920 bytes dynamic
    const uint32_t sm32 = smem_u32_(sm);
    const int tid  = threadIdx.x;
    const int wid  = tid >> 5, lane = tid & 31;
    const int g    = lane >> 2;
    const int t2   = (lane & 3) * 2;
    const int brow = blockIdx.y * 128, bcol = blockIdx.x * 128;
    const int warp_m = (wid >> 2) * 64;
    const int warp_n = (wid & 3) * 32;

    const __nv_bfloat16* gptr[4] = { Ah, Al, Bh, Bl };

    const int arow  = (lane & 7) + 8 * ((lane >> 3) & 1);
    const int akofs = 8 * (lane >> 4);
    const uint32_t a_off = (uint32_t)((warp_m + arow) * PADR + akofs) * 2;
    const int browl = (lane & 7) + 8 * (lane >> 4);
    const int bkofs = 8 * ((lane >> 3) & 1);
    const uint32_t b_off = (uint32_t)((warp_n + browl) * PADR + bkofs) * 2;

    float acc[4][4][4];
    #pragma unroll
    for (int mt = 0; mt < 4; mt++)
        #pragma unroll
        for (int nt = 0; nt < 4; nt++)
            #pragma unroll
            for (int q = 0; q < 4; q++) acc[mt][nt][q] = 0.f;

    // stage loader: 4 planes x 128 rows x 64B data; 2048 16B-chunks, 8/thread
    auto issue = [&](int st, int kt) {
        uint32_t sb = sm32 + (uint32_t)st * STAGE * 2;
        #pragma unroll
        for (int q = 0; q < 8; q++) {
            int ch = tid + q * 256;              // 0..2047
            int p  = ch >> 9;                    // plane 0..3
            int rc = ch & 511;
            int r  = rc >> 2;                    // row 0..127
            int c  = (rc & 3) * 8;               // bf16 col 0,8,16,24
            int rbase = (p < 2) ? brow : bcol;
            uint32_t sa = sb + (uint32_t)(p * PLANE + r * PADR + c) * 2;
            const __nv_bfloat16* ga = gptr[p] + (size_t)(rbase + r) * K + kt + c;
            CP_ASYNC16(sa, ga);
        }
        CP_COMMIT();
    };

    const int NK = K / BKT;
    issue(0, 0);
    issue(1, BKT);
    CP_WAIT1();
    __syncthreads();

    for (int i = 0; i < NK; i++) {
        const int st = i & 1;
        const uint32_t sbase = sm32 + (uint32_t)st * STAGE * 2;

        #pragma unroll
        for (int kk = 0; kk < BKT; kk += 16) {
            const uint32_t kb = (uint32_t)kk * 2;
            uint32_t ah[4][4], al[4][4], bh[2][4], bl[2][4];
            #pragma unroll
            for (int mt = 0; mt < 4; mt++) {
                uint32_t ad = sbase + a_off + (uint32_t)(mt * 16 * PADR) * 2 + kb;
                ldsm4(ah[mt], ad);
                ldsm4(al[mt], ad + (uint32_t)PLANE * 2);
            }
            #pragma unroll
            for (int ntp = 0; ntp < 2; ntp++) {
                uint32_t bd = sbase + b_off + (uint32_t)((2 * PLANE) + ntp * 16 * PADR) * 2 + kb;
                ldsm4(bh[ntp], bd);
                ldsm4(bl[ntp], bd + (uint32_t)PLANE * 2);
            }

            #pragma unroll
            for (int mt = 0; mt < 4; mt++)
                #pragma unroll
                for (int nt = 0; nt < 4; nt++) {
                    const uint32_t* fh = &bh[nt >> 1][(nt & 1) * 2];
                    const uint32_t* fl = &bl[nt >> 1][(nt & 1) * 2];
                    mma16816(acc[mt][nt], ah[mt], fh);
                    mma16816(acc[mt][nt], ah[mt], fl);
                    mma16816(acc[mt][nt], al[mt], fh);
                }
        }

        __syncthreads();
        if (i + 2 < NK) issue(st, (i + 2) * BKT);
        else            CP_COMMIT();
        CP_WAIT1();
        __syncthreads();
    }

    #pragma unroll
    for (int mt = 0; mt < 4; mt++) {
        int r0 = brow + warp_m + mt * 16 + g;
        #pragma unroll
        for (int nt = 0; nt < 4; nt++) {
            int c = bcol + warp_n + nt * 8 + t2;
            float2 bv = *(const float2*)&bias[c];
            float2 o0, o1;
            o0.x = acc[mt][nt][0] + bv.x;
            o0.y = acc[mt][nt][1] + bv.y;
            o1.x = acc[mt][nt][2] + bv.x;
            o1.y = acc[mt][nt][3] + bv.y;
            if (RESID) {
                float2 rv0 = *(const float2*)&resid[(size_t)r0 * N + c];
                float2 rv1 = *(const float2*)&resid[(size_t)(r0 + 8) * N + c];
                o0.x += rv0.x; o0.y += rv0.y;
                o1.x += rv1.x; o1.y += rv1.y;
            }
            *(float2*)&Cout[(size_t)r0 * N + c]       = o0;
            *(float2*)&Cout[(size_t)(r0 + 8) * N + c] = o1;
        }
    }
}

// ---------------- K1: per-chunk final g-states (conv fused) ------------------
// g-recurrence: g = sA*g + xcv  (h = sB*g; sB divided out -> 16 FMA/t)
__global__ __launch_bounds__(256)
void scan_state_kernel(const float* __restrict__ xp,
                       const float* __restrict__ A,
                       const float* __restrict__ convw,
                       float* __restrict__ hloc)
{
    int tid = blockIdx.x * blockDim.x + threadIdx.x;   // b*NCH*EE + c*EE + e
    int e  = tid % EE;
    int bc = tid / EE;
    int c  = bc % NCH;
    int b  = bc / NCH;

    float sA[DSTATE], g[DSTATE];
    #pragma unroll
    for (int n = 0; n < DSTATE; n++) {
        sA[n] = sigmoidf_(A[e * DSTATE + n]);
        g[n] = 0.f;
    }
    float w0 = convw[e * 4 + 0];
    float w1 = convw[e * 4 + 1];
    float w2 = convw[e * 4 + 2];
    float w3 = convw[e * 4 + 3];

    const int t0 = c * CH;
    const float* xb = xp + (size_t)b * LL * EE + e;
    float xm1 = (t0 >= 1) ? xb[(size_t)(t0 - 1) * EE] : 0.f;
    float xm2 = (t0 >= 2) ? xb[(size_t)(t0 - 2) * EE] : 0.f;
    float xm3 = (t0 >= 3) ? xb[(size_t)(t0 - 3) * EE] : 0.f;

    const float* xq = xb + (size_t)t0 * EE;

    #pragma unroll
    for (int tb = 0; tb < CH; tb += 8) {
        float xv[8];
        #pragma unroll
        for (int j = 0; j < 8; j++)
            xv[j] = xq[(size_t)(tb + j) * EE];

        #pragma unroll
        for (int j = 0; j < 8; j++) {
            float xcv = xv[j] * w3 + xm1 * w2 + xm2 * w1 + xm3 * w0;
            xm3 = xm2; xm2 = xm1; xm1 = xv[j];
            #pragma unroll
            for (int n = 0; n < DSTATE; n++)
                g[n] = fmaf(sA[n], g[n], xcv);
        }
    }

    float* hp = hloc + (((size_t)b * NCH + c) * DSTATE) * EE + e;
    #pragma unroll
    for (int n = 0; n < DSTATE; n++)
        hp[(size_t)n * EE] = g[n];
}

// ---------------- K2: combine chunk g-states sequentially --------------------
__global__ void chunk_combine_kernel(const float* __restrict__ hloc,
                                     const float* __restrict__ A,
                                     float* __restrict__ hin)
{
    int tid = blockIdx.x * blockDim.x + threadIdx.x;   // b*DSTATE*EE + n*EE + e
    int e  = tid % EE;
    int bn = tid / EE;
    int n  = bn % DSTATE;
    int b  = bn / DSTATE;

    float sA = sigmoidf_(A[e * DSTATE + n]);
    float pw = sA;
    #pragma unroll
    for (int i = 0; i < 5; i++) pw *= pw;              // sA^32 (CH=32)

    size_t base = ((size_t)b * NCH * DSTATE + n) * EE + e;
    const size_t cstride = (size_t)DSTATE * EE;

    float h = 0.f;
    #pragma unroll
    for (int c = 0; c < NCH; c++) {
        hin[base + c * cstride] = h;
        h = fmaf(pw, h, hloc[base + c * cstride]);
    }
}

// ---------------- K3: full g-scan from hin, y = sum sCB*g, bf16 split --------
__global__ __launch_bounds__(256)
void scan_out_kernel(const float* __restrict__ xp,
                     const float* __restrict__ hin,
                     const float* __restrict__ A,
                     const float* __restrict__ Bp,
                     const float* __restrict__ C,
                     const float* __restrict__ convw,
                     __nv_bfloat16* __restrict__ yh,
                     __nv_bfloat16* __restrict__ yl)
{
    int tid = blockIdx.x * blockDim.x + threadIdx.x;   // b*NCH*EE + c*EE + e
    int e  = tid % EE;
    int bc = tid / EE;
    int c  = bc % NCH;
    int b  = bc / NCH;

    float sA[DSTATE], sCB[DSTATE], g[DSTATE];
    const float* hp = hin + (((size_t)b * NCH + c) * DSTATE) * EE + e;
    #pragma unroll
    for (int n = 0; n < DSTATE; n++) {
        sA[n]  = sigmoidf_(A[e * DSTATE + n]);
        sCB[n] = sigmoidf_(C[e * DSTATE + n]) * sigmoidf_(Bp[e * DSTATE + n]);
        g[n]   = (c > 0) ? hp[(size_t)n * EE] : 0.f;
    }
    float w0 = convw[e * 4 + 0];
    float w1 = convw[e * 4 + 1];
    float w2 = convw[e * 4 + 2];
    float w3 = convw[e * 4 + 3];

    const int t0 = c * CH;
    const float* xb = xp + (size_t)b * LL * EE + e;
    float xm1 = (t0 >= 1) ? xb[(size_t)(t0 - 1) * EE] : 0.f;
    float xm2 = (t0 >= 2) ? xb[(size_t)(t0 - 2) * EE] : 0.f;
    float xm3 = (t0 >= 3) ? xb[(size_t)(t0 - 3) * EE] : 0.f;

    const float* xq = xb + (size_t)t0 * EE;
    size_t obase = ((size_t)b * LL + t0) * EE + e;
    __nv_bfloat16* yhb = yh + obase;
    __nv_bfloat16* ylb = yl + obase;

    #pragma unroll
    for (int tb = 0; tb < CH; tb += 8) {
        float xv[8];
        #pragma unroll
        for (int j = 0; j < 8; j++)
            xv[j] = xq[(size_t)(tb + j) * EE];

        #pragma unroll
        for (int j = 0; j < 8; j++) {
            float xcv = xv[j] * w3 + xm1 * w2 + xm2 * w1 + xm3 * w0;
            xm3 = xm2; xm2 = xm1; xm1 = xv[j];

            float a0 = 0.f, a1 = 0.f, a2 = 0.f, a3 = 0.f;
            #pragma unroll
            for (int n = 0; n < DSTATE; n += 4) {
                g[n + 0] = fmaf(sA[n + 0], g[n + 0], xcv);
                g[n + 1] = fmaf(sA[n + 1], g[n + 1], xcv);
                g[n + 2] = fmaf(sA[n + 2], g[n + 2], xcv);
                g[n + 3] = fmaf(sA[n + 3], g[n + 3], xcv);
                a0 = fmaf(sCB[n + 0], g[n + 0], a0);
                a1 = fmaf(sCB[n + 1], g[n + 1], a1);
                a2 = fmaf(sCB[n + 2], g[n + 2], a2);
                a3 = fmaf(sCB[n + 3], g[n + 3], a3);
            }
            float v = (a0 + a1) + (a2 + a3);
            __nv_bfloat16 hv = __float2bfloat16(v);
            yhb[(size_t)(tb + j) * EE] = hv;
            ylb[(size_t)(tb + j) * EE] = __float2bfloat16(v - __bfloat162float(hv));
        }
    }
}

// ---------------- launch -----------------------------------------------------
extern "C" void kernel_launch(void* const* d_in, const int* in_sizes, int n_in,
                              void* d_out, int out_size)
{
    const float* x      = (const float*)d_in[0];
    const float* gamma  = (const float*)d_in[1];
    const float* W_in   = (const float*)d_in[2];
    const float* b_in   = (const float*)d_in[3];
    const float* conv_w = (const float*)d_in[4];
    const float* A      = (const float*)d_in[5];
    const float* Bp     = (const float*)d_in[6];
    const float* C      = (const float*)d_in[7];
    const float* W_out  = (const float*)d_in[8];
    const float* b_out  = (const float*)d_in[9];
    float* out = (float*)d_out;

    float *xp, *hloc, *hin;
    __nv_bfloat16 *xnh, *xnl, *winh, *winl, *wouth, *woutl, *yh, *yl;
    cudaGetSymbolAddress((void**)&xp,    g_xp);
    cudaGetSymbolAddress((void**)&hloc,  g_hloc);
    cudaGetSymbolAddress((void**)&hin,   g_hin);
    cudaGetSymbolAddress((void**)&xnh,   g_xnh);
    cudaGetSymbolAddress((void**)&xnl,   g_xnl);
    cudaGetSymbolAddress((void**)&winh,  g_winh);
    cudaGetSymbolAddress((void**)&winl,  g_winl);
    cudaGetSymbolAddress((void**)&wouth, g_wouth);
    cudaGetSymbolAddress((void**)&woutl, g_woutl);
    cudaGetSymbolAddress((void**)&yh,    g_yh);
    cudaGetSymbolAddress((void**)&yl,    g_yl);

    // idempotent, capture-safe, no static state
    cudaFuncSetAttribute(gemm_mma_kernel<false>,
                         cudaFuncAttributeMaxDynamicSharedMemorySize, SMEM_GEMM);
    cudaFuncSetAttribute(gemm_mma_kernel<true>,
                         cudaFuncAttributeMaxDynamicSharedMemorySize, SMEM_GEMM);

    // 1. rmsnorm -> bf16 hi/lo
    rmsnorm_kernel<<<BL, 256>>>(x, gamma, xnh, xnl);

    // 1b. convert weights -> bf16 hi/lo
    convert_w_kernel<<<(2 * EE * DIM + 255) / 256, 256>>>(W_in, W_out,
                                                          winh, winl, wouth, woutl);

    // 2. in-proj (HMMA): xp = xn @ W_in^T + b_in
    {
        dim3 grid(EE / 128, BL / 128);
        gemm_mma_kernel<false><<<grid, 256, SMEM_GEMM>>>(xnh, xnl, winh, winl,
                                                         b_in, nullptr, xp, EE, DIM);
    }

    // 3. chunked g-scan (conv fused)
    {
        int threads = BB * NCH * EE;                   // 196608
        scan_state_kernel<<<threads / 256, 256>>>(xp, A, conv_w, hloc);
    }
    {
        int threads = BB * DSTATE * EE;                // 49152
        chunk_combine_kernel<<<threads / 256, 256>>>(hloc, A, hin);
    }
    {
        int threads = BB * NCH * EE;
        scan_out_kernel<<<threads / 256, 256>>>(xp, hin, A, Bp, C, conv_w, yh, yl);
    }

    // 4. out-proj + residual (HMMA): out = y @ W_out^T + b_out + x
    {
        dim3 grid(DIM / 128, BL / 128);
        gemm_mma_kernel<true><<<grid, 256, SMEM_GEMM>>>(yh, yl, wouth, woutl,
                                                        b_out, x, out, DIM, EE);
    }
}